// round 7
// baseline (speedup 1.0000x reference)
#include <cuda_runtime.h>
#include <cstdint>

// ESSAttn: b=8, C=64, H=W=256, N=65536
// x, out: [b][C][N]  (b<<22 | c<<16 | n)
// scratch q2n,k2d,v: [b][N][C]  (b<<22 | n<<6 | c)

#define NPIX 65536
#define NBAT 8

typedef unsigned long long u64;

// ---------------- scratch ----------------
__device__ float g_q2n[(size_t)NBAT * 64 * NPIX];
__device__ float g_k2d[(size_t)NBAT * 64 * NPIX];
__device__ float g_v  [(size_t)NBAT * 64 * NPIX];
__device__ float g_M  [NBAT * 64 * 64];
__device__ float g_css[NBAT * 64];
__device__ float g_Wcat[NBAT * 64 * 128];   // [b][j][ 0..63: wln | 64..127: WK/256 ]

// ---------------- packed fp32 helpers ----------------
__device__ __forceinline__ u64 ffma2(u64 a, u64 b, u64 c) {
    u64 d;
    asm("fma.rn.f32x2 %0, %1, %2, %3;" : "=l"(d) : "l"(a), "l"(b), "l"(c));
    return d;
}
__device__ __forceinline__ u64 fadd2(u64 a, u64 b) {
    u64 d;
    asm("add.rn.f32x2 %0, %1, %2;" : "=l"(d) : "l"(a), "l"(b));
    return d;
}
__device__ __forceinline__ float2 unpack2(u64 v) {
    float lo, hi;
    asm("mov.b64 {%0, %1}, %2;" : "=f"(lo), "=f"(hi) : "l"(v));
    return make_float2(lo, hi);
}
__device__ __forceinline__ float hsum1(u64 v) {
    float2 r = unpack2(v);
    return r.x + r.y;
}
__device__ __forceinline__ float hsum2(u64 a, u64 b) {
    float2 r = unpack2(fadd2(a, b));
    return r.x + r.y;
}
__device__ __forceinline__ u64 lds_u64(const float* p) {
    return *reinterpret_cast<const u64*>(p);
}

// ---------------------------------------------------------------------------
// qkv: per CTA 128 pixels, C[128,192] = x @ Wqkv^T in 3 passes of 64 outputs.
// Register-blocked: 256 thr, tile 8px x 4out, k-packed FFMA2.
// tx = tid&15 -> pixel lanes (px = tx + 16*pp); ty = tid>>4 -> out group (j = 4ty+jj)
// smem floats: A[128*66] | Wp[64*66] | C[64*131] | sB[192]
__global__ __launch_bounds__(256, 2) void essa_qkv(const float* __restrict__ x,
                                                   const float* __restrict__ wqkv,
                                                   const float* __restrict__ bqkv) {
    extern __shared__ float sm[];
    float* A  = sm;                 // 8448
    float* Wp = sm + 8448;          // 4224
    float* C  = sm + 12672;         // 8384
    float* sB = sm + 21056;         // 192  (total 21248 fl = 84992 B)

    const int tid = threadIdx.x;
    const int tx = tid & 15, ty = tid >> 4;
    const int b = blockIdx.y;
    const int n0 = blockIdx.x << 7;
    const size_t xbase = (size_t)b << 22;

    if (blockIdx.x == 0 && b == 0) {    // zero accumulators for kvacc
        for (int i = tid; i < NBAT * 64 * 64; i += 256) g_M[i] = 0.f;
        for (int i = tid; i < NBAT * 64; i += 256) g_css[i] = 0.f;
    }

    // A fill: A[px][k], pad 66
    for (int i = tid; i < 8192; i += 256) {
        int k = i >> 7, px = i & 127;
        A[px * 66 + k] = x[xbase + ((size_t)k << 16) + n0 + px];
    }
    // W pass 0 (Q rows) + bias
    for (int i = tid; i < 4096; i += 256) {
        int j = i >> 6, k = i & 63;
        Wp[j * 66 + k] = wqkv[i];
    }
    if (tid < 192) sB[tid] = bqkv[tid];
    __syncthreads();

#pragma unroll 1
    for (int pass = 0; pass < 3; ++pass) {
        u64 acc[8][4];
#pragma unroll
        for (int pp = 0; pp < 8; ++pp)
#pragma unroll
            for (int jj = 0; jj < 4; ++jj) acc[pp][jj] = 0;

#pragma unroll 8
        for (int k2 = 0; k2 < 32; ++k2) {
            u64 b0 = lds_u64(Wp + (4 * ty + 0) * 66 + 2 * k2);
            u64 b1 = lds_u64(Wp + (4 * ty + 1) * 66 + 2 * k2);
            u64 b2 = lds_u64(Wp + (4 * ty + 2) * 66 + 2 * k2);
            u64 b3 = lds_u64(Wp + (4 * ty + 3) * 66 + 2 * k2);
#pragma unroll
            for (int pp = 0; pp < 8; ++pp) {
                u64 a = lds_u64(A + (tx + 16 * pp) * 66 + 2 * k2);
                acc[pp][0] = ffma2(a, b0, acc[pp][0]);
                acc[pp][1] = ffma2(a, b1, acc[pp][1]);
                acc[pp][2] = ffma2(a, b2, acc[pp][2]);
                acc[pp][3] = ffma2(a, b3, acc[pp][3]);
            }
        }

        if (pass < 2) {
            // stage to C[j][px], pad 131
#pragma unroll
            for (int jj = 0; jj < 4; ++jj)
#pragma unroll
                for (int pp = 0; pp < 8; ++pp)
                    C[(4 * ty + jj) * 131 + tx + 16 * pp] = hsum1(acc[pp][jj]);
            __syncthreads();

            if (tid < 128) {
                // stats for pixel px = tid
                const int px = tid;
                const size_t rownc = xbase + ((size_t)(n0 + px) << 6);
                float rv[64];
                const int boff = pass * 64;
#pragma unroll 8
                for (int j = 0; j < 64; ++j) rv[j] = C[j * 131 + px] + sB[boff + j];
                float mean = 0.f;
#pragma unroll 8
                for (int j = 0; j < 64; ++j) mean += rv[j];
                mean *= (1.f / 64.f);
                float ss = 0.f;
#pragma unroll 8
                for (int j = 0; j < 64; ++j) { float t = rv[j] - mean; t = t * t; rv[j] = t; ss += t; }
                float inv = 1.f / (ss + 1e-7f);
                if (pass == 0) {
                    float nr = 0.f;
#pragma unroll 8
                    for (int j = 0; j < 64; ++j) { float t = rv[j] * inv; nr = fmaf(t, t, nr); }
                    float sc = inv / fmaxf(sqrtf(nr), 1e-12f);
                    float4* dq = reinterpret_cast<float4*>(g_q2n + rownc);
#pragma unroll
                    for (int t = 0; t < 16; ++t)
                        dq[t] = make_float4(rv[4 * t] * sc, rv[4 * t + 1] * sc,
                                            rv[4 * t + 2] * sc, rv[4 * t + 3] * sc);
                } else {
                    float4* dk = reinterpret_cast<float4*>(g_k2d + rownc);
#pragma unroll
                    for (int t = 0; t < 16; ++t)
                        dk[t] = make_float4(rv[4 * t] * inv, rv[4 * t + 1] * inv,
                                            rv[4 * t + 2] * inv, rv[4 * t + 3] * inv);
                }
            } else {
                // load next pass weights
                const float* src = wqkv + 4096 * (pass + 1);
                for (int i = tid - 128; i < 4096; i += 128) {
                    int j = i >> 6, k = i & 63;
                    Wp[j * 66 + k] = src[i];
                }
            }
            __syncthreads();
        } else {
            // V: direct register -> global (scattered float4 rows)
#pragma unroll
            for (int pp = 0; pp < 8; ++pp) {
                const int n = n0 + tx + 16 * pp;
                float4 v4 = make_float4(hsum1(acc[pp][0]) + sB[128 + 4 * ty + 0],
                                        hsum1(acc[pp][1]) + sB[128 + 4 * ty + 1],
                                        hsum1(acc[pp][2]) + sB[128 + 4 * ty + 2],
                                        hsum1(acc[pp][3]) + sB[128 + 4 * ty + 3]);
                *reinterpret_cast<float4*>(g_v + xbase + ((size_t)n << 6) + 4 * ty) = v4;
            }
        }
    }
}

// ---------------------------------------------------------------------------
// kvacc: M[c][d] += sum_n k2d[n][c]*v[n][d]; css[c] += sum k2d^2
__global__ __launch_bounds__(256) void essa_kvacc() {
    const int b = blockIdx.y;
    const int n0 = blockIdx.x << 9;
    const size_t base = (size_t)b << 22;

    __shared__ float ks[64 * 33];                  // [c][nn]
    __shared__ __align__(16) float vs[32 * 68];    // [nn][d]

    const int tid = threadIdx.x;
    const int ty = tid >> 4, tx = tid & 15;
    const int c0 = ty << 2, d0 = tx << 2;

    u64 acc[4][2];
#pragma unroll
    for (int i = 0; i < 4; ++i) { acc[i][0] = 0; acc[i][1] = 0; }
    float cssr = 0.f;

    for (int t = 0; t < 16; ++t) {
        const int nb = n0 + (t << 5);
        __syncthreads();
        for (int i = tid; i < 512; i += 256) {
            int nn = i >> 4, c4 = (i & 15) << 2;
            size_t g = base + ((size_t)(nb + nn) << 6) + c4;
            float4 kk = *reinterpret_cast<const float4*>(g_k2d + g);
            float4 vv = *reinterpret_cast<const float4*>(g_v + g);
            ks[(c4 + 0) * 33 + nn] = kk.x;
            ks[(c4 + 1) * 33 + nn] = kk.y;
            ks[(c4 + 2) * 33 + nn] = kk.z;
            ks[(c4 + 3) * 33 + nn] = kk.w;
            *reinterpret_cast<float4*>(vs + nn * 68 + c4) = vv;
        }
        __syncthreads();
        const float* kp = ks + c0 * 33;
#pragma unroll 4
        for (int nn = 0; nn < 32; ++nn) {
            ulonglong2 v01 = *reinterpret_cast<const ulonglong2*>(vs + nn * 68 + d0);
            float k0 = kp[nn], k1 = kp[33 + nn], k2 = kp[66 + nn], k3 = kp[99 + nn];
            u64 kk0, kk1, kk2, kk3;
            asm("mov.b64 %0, {%1, %1};" : "=l"(kk0) : "f"(k0));
            asm("mov.b64 %0, {%1, %1};" : "=l"(kk1) : "f"(k1));
            asm("mov.b64 %0, {%1, %1};" : "=l"(kk2) : "f"(k2));
            asm("mov.b64 %0, {%1, %1};" : "=l"(kk3) : "f"(k3));
            acc[0][0] = ffma2(kk0, v01.x, acc[0][0]); acc[0][1] = ffma2(kk0, v01.y, acc[0][1]);
            acc[1][0] = ffma2(kk1, v01.x, acc[1][0]); acc[1][1] = ffma2(kk1, v01.y, acc[1][1]);
            acc[2][0] = ffma2(kk2, v01.x, acc[2][0]); acc[2][1] = ffma2(kk2, v01.y, acc[2][1]);
            acc[3][0] = ffma2(kk3, v01.x, acc[3][0]); acc[3][1] = ffma2(kk3, v01.y, acc[3][1]);
        }
        if (tid < 64) {
            const float* cp = ks + tid * 33;
#pragma unroll 8
            for (int nn = 0; nn < 32; ++nn) { float u = cp[nn]; cssr = fmaf(u, u, cssr); }
        }
    }

    float* Mp = g_M + (b << 12);
#pragma unroll
    for (int i = 0; i < 4; ++i) {
        float2 a0 = unpack2(acc[i][0]), a1 = unpack2(acc[i][1]);
        atomicAdd(&Mp[(c0 + i) * 64 + d0 + 0], a0.x);
        atomicAdd(&Mp[(c0 + i) * 64 + d0 + 1], a0.y);
        atomicAdd(&Mp[(c0 + i) * 64 + d0 + 2], a1.x);
        atomicAdd(&Mp[(c0 + i) * 64 + d0 + 3], a1.y);
    }
    if (tid < 64) atomicAdd(&g_css[(b << 6) + tid], cssr);
}

// ---------------------------------------------------------------------------
// wcat: Wcat[b][j][0..63] = wln[j][:];  Wcat[b][j][64+c] = (sum_d M[c][d]*wln[j][d]) / (nrm_c*256)
__global__ void essa_wcat(const float* __restrict__ wln) {
    __shared__ float sM[4096], sW[4096], sInv[64];
    const int b = blockIdx.x;
    const int tid = threadIdx.x;

    for (int i = tid; i < 4096; i += 256) {
        sM[i] = g_M[(b << 12) + i];
        sW[i] = wln[i];
    }
    if (tid < 64)
        sInv[tid] = 1.f / (fmaxf(sqrtf(g_css[(b << 6) + tid]), 1e-12f) * 256.f);
    __syncthreads();

    float* Wc = g_Wcat + (b << 13);
    for (int i = tid; i < 4096; i += 256) {
        int j = i >> 6, d = i & 63;
        Wc[j * 128 + d] = sW[i];
    }
#pragma unroll 1
    for (int t = 0; t < 16; ++t) {
        int i = tid + (t << 8);
        int j = i >> 6, c = i & 63;
        u64 s0 = 0, s1 = 0;
#pragma unroll
        for (int dd = 0; dd < 16; ++dd) {
            s0 = ffma2(lds_u64(sM + c * 64 + 4 * dd),     lds_u64(sW + j * 64 + 4 * dd),     s0);
            s1 = ffma2(lds_u64(sM + c * 64 + 4 * dd + 2), lds_u64(sW + j * 64 + 4 * dd + 2), s1);
        }
        Wc[j * 128 + 64 + c] = hsum2(s0, s1) * sInv[c];
    }
}

// ---------------------------------------------------------------------------
// out: single K=128 GEMM: out[n][j] = [v|q2n][n][:] . Wcat[b][j][:] + bln[j]
// smem floats: A[128*130] | Wc[64*130] | sBl[64]; C[64*131] reuses A region.
__global__ __launch_bounds__(256, 2) void essa_out(const float* __restrict__ bln,
                                                   float* __restrict__ out) {
    extern __shared__ float sm[];
    float* A   = sm;                 // 16640
    float* Wc  = sm + 16640;         // 8320
    float* sBl = sm + 24960;         // 64   (total 25024 fl = 100096 B)
    float* C   = sm;                 // reuse (8384 <= 16640)

    const int tid = threadIdx.x;
    const int tx = tid & 15, ty = tid >> 4;
    const int b = blockIdx.y;
    const int n0 = blockIdx.x << 7;
    const size_t base = (size_t)b << 22;

    for (int i = tid; i < 8192; i += 256) {
        int px = i >> 6, c = i & 63;
        size_t r = base + ((size_t)(n0 + px) << 6) + c;
        A[px * 130 + c]      = g_v[r];
        A[px * 130 + 64 + c] = g_q2n[r];
    }
    for (int i = tid; i < 8192; i += 256) {
        int j = i >> 7, k = i & 127;
        Wc[j * 130 + k] = g_Wcat[(b << 13) + i];
    }
    if (tid < 64) sBl[tid] = bln[tid];
    __syncthreads();

    u64 acc[8][4];
#pragma unroll
    for (int pp = 0; pp < 8; ++pp)
#pragma unroll
        for (int jj = 0; jj < 4; ++jj) acc[pp][jj] = 0;

#pragma unroll 8
    for (int k2 = 0; k2 < 64; ++k2) {
        u64 b0 = lds_u64(Wc + (4 * ty + 0) * 130 + 2 * k2);
        u64 b1 = lds_u64(Wc + (4 * ty + 1) * 130 + 2 * k2);
        u64 b2 = lds_u64(Wc + (4 * ty + 2) * 130 + 2 * k2);
        u64 b3 = lds_u64(Wc + (4 * ty + 3) * 130 + 2 * k2);
#pragma unroll
        for (int pp = 0; pp < 8; ++pp) {
            u64 a = lds_u64(A + (tx + 16 * pp) * 130 + 2 * k2);
            acc[pp][0] = ffma2(a, b0, acc[pp][0]);
            acc[pp][1] = ffma2(a, b1, acc[pp][1]);
            acc[pp][2] = ffma2(a, b2, acc[pp][2]);
            acc[pp][3] = ffma2(a, b3, acc[pp][3]);
        }
    }
    __syncthreads();   // all A reads done; reuse as C

#pragma unroll
    for (int jj = 0; jj < 4; ++jj)
#pragma unroll
        for (int pp = 0; pp < 8; ++pp)
            C[(4 * ty + jj) * 131 + tx + 16 * pp] = hsum1(acc[pp][jj]);
    __syncthreads();

    for (int i = tid; i < 8192; i += 256) {
        int j = i >> 7, px = i & 127;
        out[base + ((size_t)j << 16) + n0 + px] = C[j * 131 + px] + sBl[j];
    }
}

// ---------------------------------------------------------------------------
extern "C" void kernel_launch(void* const* d_in, const int* in_sizes, int n_in,
                              void* d_out, int out_size) {
    const float* x    = (const float*)d_in[0];
    const float* wqkv = (const float*)d_in[1];
    const float* bqkv = (const float*)d_in[2];
    const float* wln  = (const float*)d_in[3];
    const float* bln  = (const float*)d_in[4];
    float* out = (float*)d_out;

    cudaFuncSetAttribute(essa_qkv, cudaFuncAttributeMaxDynamicSharedMemorySize, 84992);
    cudaFuncSetAttribute(essa_out, cudaFuncAttributeMaxDynamicSharedMemorySize, 100096);

    dim3 gridQ(NPIX / 128, NBAT);
    essa_qkv<<<gridQ, 256, 84992>>>(x, wqkv, bqkv);

    dim3 gridM(NPIX / 512, NBAT);
    essa_kvacc<<<gridM, 256>>>();

    essa_wcat<<<NBAT, 256>>>(wln);

    essa_out<<<gridQ, 256, 100096>>>(bln, out);
}

// round 8
// speedup vs baseline: 1.3215x; 1.3215x over previous
#include <cuda_runtime.h>
#include <cstdint>

// ESSAttn: b=8, C=64, H=W=256, N=65536
// x, out: [b][C][N]  (b<<22 | c<<16 | n)
// scratch q2n,k2d,v: [b][N][C]  (b<<22 | n<<6 | c)

#define NPIX 65536
#define NBAT 8

typedef unsigned long long u64;

// ---------------- scratch ----------------
__device__ float g_q2n[(size_t)NBAT * 64 * NPIX];
__device__ float g_k2d[(size_t)NBAT * 64 * NPIX];
__device__ float g_v  [(size_t)NBAT * 64 * NPIX];
__device__ float g_M  [NBAT * 64 * 64];
__device__ float g_css[NBAT * 64];
__device__ float g_Wcat[NBAT * 64 * 128];   // [b][j][ 0..63: wln | 64..127: WK/256 ]

// ---------------- packed fp32 helpers ----------------
__device__ __forceinline__ u64 ffma2(u64 a, u64 b, u64 c) {
    u64 d;
    asm("fma.rn.f32x2 %0, %1, %2, %3;" : "=l"(d) : "l"(a), "l"(b), "l"(c));
    return d;
}
__device__ __forceinline__ u64 fadd2(u64 a, u64 b) {
    u64 d;
    asm("add.rn.f32x2 %0, %1, %2;" : "=l"(d) : "l"(a), "l"(b));
    return d;
}
__device__ __forceinline__ float2 unpack2(u64 v) {
    float lo, hi;
    asm("mov.b64 {%0, %1}, %2;" : "=f"(lo), "=f"(hi) : "l"(v));
    return make_float2(lo, hi);
}
__device__ __forceinline__ float hsum1(u64 v) {
    float2 r = unpack2(v);
    return r.x + r.y;
}
__device__ __forceinline__ float hsum2(u64 a, u64 b) {
    float2 r = unpack2(fadd2(a, b));
    return r.x + r.y;
}
__device__ __forceinline__ u64 lds_u64(const float* p) {
    return *reinterpret_cast<const u64*>(p);
}
__device__ __forceinline__ ulonglong2 lds_u128(const float* p) {
    return *reinterpret_cast<const ulonglong2*>(p);
}

// ---------------------------------------------------------------------------
// qkv: per CTA 128 px, C[128,192] = x @ Wqkv^T, 3 passes of 64 outputs.
// Reg tile 8px x 4out, LDS.128 feeds, stats split 2-threads-per-pixel.
// smem floats: A[128*68] | Wp[64*68] | C[64*131] | sB[192]  = 86528 B
__global__ __launch_bounds__(256, 2) void essa_qkv(const float* __restrict__ x,
                                                   const float* __restrict__ wqkv,
                                                   const float* __restrict__ bqkv) {
    extern __shared__ float sm[];
    float* A  = sm;                  // 8704
    float* Wp = sm + 8704;           // 4352
    float* C  = sm + 13056;          // 8384
    float* sB = sm + 21440;          // 192

    const int tid = threadIdx.x;
    const int tx = tid & 15, ty = tid >> 4;
    const int b = blockIdx.y;
    const int n0 = blockIdx.x << 7;
    const size_t xbase = (size_t)b << 22;

    if (blockIdx.x == 0 && b == 0) {     // zero accumulators for kvacc
        for (int i = tid; i < NBAT * 64 * 64; i += 256) g_M[i] = 0.f;
        for (int i = tid; i < NBAT * 64; i += 256) g_css[i] = 0.f;
    }

    for (int i = tid; i < 8192; i += 256) {
        int k = i >> 7, px = i & 127;
        A[px * 68 + k] = x[xbase + ((size_t)k << 16) + n0 + px];
    }
    for (int i = tid; i < 4096; i += 256) {
        int j = i >> 6, k = i & 63;
        Wp[j * 68 + k] = wqkv[i];
    }
    if (tid < 192) sB[tid] = bqkv[tid];
    __syncthreads();

    // stats lane mapping: 2 threads per pixel
    const int lane = tid & 31, w = tid >> 5;
    const int spx = (w << 4) + (lane >> 1);
    const int h = lane & 1;

#pragma unroll 1
    for (int pass = 0; pass < 3; ++pass) {
        u64 acc[8][4];
#pragma unroll
        for (int pp = 0; pp < 8; ++pp)
#pragma unroll
            for (int jj = 0; jj < 4; ++jj) acc[pp][jj] = 0;

#pragma unroll 4
        for (int k4 = 0; k4 < 16; ++k4) {
            ulonglong2 b0 = lds_u128(Wp + (4 * ty + 0) * 68 + 4 * k4);
            ulonglong2 b1 = lds_u128(Wp + (4 * ty + 1) * 68 + 4 * k4);
            ulonglong2 b2 = lds_u128(Wp + (4 * ty + 2) * 68 + 4 * k4);
            ulonglong2 b3 = lds_u128(Wp + (4 * ty + 3) * 68 + 4 * k4);
#pragma unroll
            for (int pp = 0; pp < 8; ++pp) {
                ulonglong2 a = lds_u128(A + (tx + 16 * pp) * 68 + 4 * k4);
                acc[pp][0] = ffma2(a.x, b0.x, acc[pp][0]);
                acc[pp][0] = ffma2(a.y, b0.y, acc[pp][0]);
                acc[pp][1] = ffma2(a.x, b1.x, acc[pp][1]);
                acc[pp][1] = ffma2(a.y, b1.y, acc[pp][1]);
                acc[pp][2] = ffma2(a.x, b2.x, acc[pp][2]);
                acc[pp][2] = ffma2(a.y, b2.y, acc[pp][2]);
                acc[pp][3] = ffma2(a.x, b3.x, acc[pp][3]);
                acc[pp][3] = ffma2(a.y, b3.y, acc[pp][3]);
            }
        }

        if (pass < 2) {
            __syncthreads();    // Wp reads done (before reload below)
#pragma unroll
            for (int jj = 0; jj < 4; ++jj)
#pragma unroll
                for (int pp = 0; pp < 8; ++pp)
                    C[(4 * ty + jj) * 131 + tx + 16 * pp] = hsum1(acc[pp][jj]);
            __syncthreads();

            // W reload for next pass (all threads, overlaps stats below)
            {
                const float* src = wqkv + 4096 * (pass + 1);
                for (int i = tid; i < 4096; i += 256) {
                    int j = i >> 6, k = i & 63;
                    Wp[j * 68 + k] = src[i];
                }
            }
            // stats: thread handles channels h*32 .. h*32+31 of pixel spx
            {
                const int boff = pass * 64, j0 = h << 5;
                const size_t rownc = xbase + ((size_t)(n0 + spx) << 6);
                float rv[32];
                float part = 0.f;
#pragma unroll
                for (int t = 0; t < 32; ++t) {
                    rv[t] = C[(j0 + t) * 131 + spx] + sB[boff + j0 + t];
                    part += rv[t];
                }
                float mean = (part + __shfl_xor_sync(0xFFFFFFFFu, part, 1)) * (1.f / 64.f);
                float ss = 0.f;
#pragma unroll
                for (int t = 0; t < 32; ++t) {
                    float u = rv[t] - mean;
                    u = u * u;
                    rv[t] = u;
                    ss += u;
                }
                ss += __shfl_xor_sync(0xFFFFFFFFu, ss, 1);
                float inv = 1.f / (ss + 1e-7f);
                float scale;
                if (pass == 0) {
                    float nr = 0.f;
#pragma unroll
                    for (int t = 0; t < 32; ++t) {
                        float u = rv[t] * inv;
                        nr = fmaf(u, u, nr);
                    }
                    nr += __shfl_xor_sync(0xFFFFFFFFu, nr, 1);
                    scale = inv / fmaxf(sqrtf(nr), 1e-12f);
                } else {
                    scale = inv;
                }
                float* dst = (pass == 0 ? g_q2n : g_k2d) + rownc + j0;
#pragma unroll
                for (int t = 0; t < 8; ++t)
                    reinterpret_cast<float4*>(dst)[t] =
                        make_float4(rv[4 * t] * scale, rv[4 * t + 1] * scale,
                                    rv[4 * t + 2] * scale, rv[4 * t + 3] * scale);
            }
            __syncthreads();
        } else {
            // V: direct register -> global
#pragma unroll
            for (int pp = 0; pp < 8; ++pp) {
                const int n = n0 + tx + 16 * pp;
                float4 v4 = make_float4(hsum1(acc[pp][0]) + sB[128 + 4 * ty + 0],
                                        hsum1(acc[pp][1]) + sB[128 + 4 * ty + 1],
                                        hsum1(acc[pp][2]) + sB[128 + 4 * ty + 2],
                                        hsum1(acc[pp][3]) + sB[128 + 4 * ty + 3]);
                *reinterpret_cast<float4*>(g_v + xbase + ((size_t)n << 6) + 4 * ty) = v4;
            }
        }
    }
}

// ---------------------------------------------------------------------------
// kvacc: M[c][d] += sum_n k2d[n][c]*v[n][d]; css[c] += sum k2d^2
__global__ __launch_bounds__(256) void essa_kvacc() {
    const int b = blockIdx.y;
    const int n0 = blockIdx.x << 9;
    const size_t base = (size_t)b << 22;

    __shared__ float ks[64 * 33];                  // [c][nn]
    __shared__ __align__(16) float vs[32 * 68];    // [nn][d]

    const int tid = threadIdx.x;
    const int ty = tid >> 4, tx = tid & 15;
    const int c0 = ty << 2, d0 = tx << 2;

    u64 acc[4][2];
#pragma unroll
    for (int i = 0; i < 4; ++i) { acc[i][0] = 0; acc[i][1] = 0; }
    float cssr = 0.f;

    for (int t = 0; t < 16; ++t) {
        const int nb = n0 + (t << 5);
        __syncthreads();
        for (int i = tid; i < 512; i += 256) {
            int nn = i >> 4, c4 = (i & 15) << 2;
            size_t g = base + ((size_t)(nb + nn) << 6) + c4;
            float4 kk = *reinterpret_cast<const float4*>(g_k2d + g);
            float4 vv = *reinterpret_cast<const float4*>(g_v + g);
            ks[(c4 + 0) * 33 + nn] = kk.x;
            ks[(c4 + 1) * 33 + nn] = kk.y;
            ks[(c4 + 2) * 33 + nn] = kk.z;
            ks[(c4 + 3) * 33 + nn] = kk.w;
            *reinterpret_cast<float4*>(vs + nn * 68 + c4) = vv;
        }
        __syncthreads();
        const float* kp = ks + c0 * 33;
#pragma unroll 4
        for (int nn = 0; nn < 32; ++nn) {
            ulonglong2 v01 = *reinterpret_cast<const ulonglong2*>(vs + nn * 68 + d0);
            float k0 = kp[nn], k1 = kp[33 + nn], k2 = kp[66 + nn], k3 = kp[99 + nn];
            u64 kk0, kk1, kk2, kk3;
            asm("mov.b64 %0, {%1, %1};" : "=l"(kk0) : "f"(k0));
            asm("mov.b64 %0, {%1, %1};" : "=l"(kk1) : "f"(k1));
            asm("mov.b64 %0, {%1, %1};" : "=l"(kk2) : "f"(k2));
            asm("mov.b64 %0, {%1, %1};" : "=l"(kk3) : "f"(k3));
            acc[0][0] = ffma2(kk0, v01.x, acc[0][0]); acc[0][1] = ffma2(kk0, v01.y, acc[0][1]);
            acc[1][0] = ffma2(kk1, v01.x, acc[1][0]); acc[1][1] = ffma2(kk1, v01.y, acc[1][1]);
            acc[2][0] = ffma2(kk2, v01.x, acc[2][0]); acc[2][1] = ffma2(kk2, v01.y, acc[2][1]);
            acc[3][0] = ffma2(kk3, v01.x, acc[3][0]); acc[3][1] = ffma2(kk3, v01.y, acc[3][1]);
        }
        if (tid < 64) {
            const float* cp = ks + tid * 33;
#pragma unroll 8
            for (int nn = 0; nn < 32; ++nn) { float u = cp[nn]; cssr = fmaf(u, u, cssr); }
        }
    }

    float* Mp = g_M + (b << 12);
#pragma unroll
    for (int i = 0; i < 4; ++i) {
        float2 a0 = unpack2(acc[i][0]), a1 = unpack2(acc[i][1]);
        atomicAdd(&Mp[(c0 + i) * 64 + d0 + 0], a0.x);
        atomicAdd(&Mp[(c0 + i) * 64 + d0 + 1], a0.y);
        atomicAdd(&Mp[(c0 + i) * 64 + d0 + 2], a1.x);
        atomicAdd(&Mp[(c0 + i) * 64 + d0 + 3], a1.y);
    }
    if (tid < 64) atomicAdd(&g_css[(b << 6) + tid], cssr);
}

// ---------------------------------------------------------------------------
// wcat: Wcat[b][j][0..63] = wln[j][:];  Wcat[b][j][64+c] = (sum_d M[c][d]*wln[j][d]) / (nrm_c*256)
__global__ void essa_wcat(const float* __restrict__ wln) {
    __shared__ float sM[4096], sW[4096], sInv[64];
    const int b = blockIdx.x;
    const int tid = threadIdx.x;

    for (int i = tid; i < 4096; i += 256) {
        sM[i] = g_M[(b << 12) + i];
        sW[i] = wln[i];
    }
    if (tid < 64)
        sInv[tid] = 1.f / (fmaxf(sqrtf(g_css[(b << 6) + tid]), 1e-12f) * 256.f);
    __syncthreads();

    float* Wc = g_Wcat + (b << 13);
    for (int i = tid; i < 4096; i += 256) {
        int j = i >> 6, d = i & 63;
        Wc[j * 128 + d] = sW[i];
    }
#pragma unroll 1
    for (int t = 0; t < 16; ++t) {
        int i = tid + (t << 8);
        int j = i >> 6, c = i & 63;
        u64 s0 = 0, s1 = 0;
#pragma unroll
        for (int dd = 0; dd < 16; ++dd) {
            s0 = ffma2(lds_u64(sM + c * 64 + 4 * dd),     lds_u64(sW + j * 64 + 4 * dd),     s0);
            s1 = ffma2(lds_u64(sM + c * 64 + 4 * dd + 2), lds_u64(sW + j * 64 + 4 * dd + 2), s1);
        }
        Wc[j * 128 + 64 + c] = hsum2(s0, s1) * sInv[c];
    }
}

// ---------------------------------------------------------------------------
// out: single K=128 GEMM: out[n][j] = [v|q2n][n][:] . Wcat[b][j][:] + bln[j]
// smem floats: A[128*132] | Wc[64*132] | sBl[64]; C[64*131] reuses A region. 101632 B
__global__ __launch_bounds__(256, 2) void essa_out(const float* __restrict__ bln,
                                                   float* __restrict__ out) {
    extern __shared__ float sm[];
    float* A   = sm;                 // 16896
    float* Wc  = sm + 16896;         // 8448
    float* sBl = sm + 25344;         // 64
    float* C   = sm;                 // reuse

    const int tid = threadIdx.x;
    const int tx = tid & 15, ty = tid >> 4;
    const int b = blockIdx.y;
    const int n0 = blockIdx.x << 7;
    const size_t base = (size_t)b << 22;

    for (int i = tid; i < 8192; i += 256) {
        int px = i >> 6, c = i & 63;
        size_t r = base + ((size_t)(n0 + px) << 6) + c;
        A[px * 132 + c]      = g_v[r];
        A[px * 132 + 64 + c] = g_q2n[r];
    }
    for (int i = tid; i < 8192; i += 256) {
        int j = i >> 7, k = i & 127;
        Wc[j * 132 + k] = g_Wcat[(b << 13) + i];
    }
    if (tid < 64) sBl[tid] = bln[tid];
    __syncthreads();

    u64 acc[8][4];
#pragma unroll
    for (int pp = 0; pp < 8; ++pp)
#pragma unroll
        for (int jj = 0; jj < 4; ++jj) acc[pp][jj] = 0;

#pragma unroll 4
    for (int k4 = 0; k4 < 32; ++k4) {
        ulonglong2 b0 = lds_u128(Wc + (4 * ty + 0) * 132 + 4 * k4);
        ulonglong2 b1 = lds_u128(Wc + (4 * ty + 1) * 132 + 4 * k4);
        ulonglong2 b2 = lds_u128(Wc + (4 * ty + 2) * 132 + 4 * k4);
        ulonglong2 b3 = lds_u128(Wc + (4 * ty + 3) * 132 + 4 * k4);
#pragma unroll
        for (int pp = 0; pp < 8; ++pp) {
            ulonglong2 a = lds_u128(A + (tx + 16 * pp) * 132 + 4 * k4);
            acc[pp][0] = ffma2(a.x, b0.x, acc[pp][0]);
            acc[pp][0] = ffma2(a.y, b0.y, acc[pp][0]);
            acc[pp][1] = ffma2(a.x, b1.x, acc[pp][1]);
            acc[pp][1] = ffma2(a.y, b1.y, acc[pp][1]);
            acc[pp][2] = ffma2(a.x, b2.x, acc[pp][2]);
            acc[pp][2] = ffma2(a.y, b2.y, acc[pp][2]);
            acc[pp][3] = ffma2(a.x, b3.x, acc[pp][3]);
            acc[pp][3] = ffma2(a.y, b3.y, acc[pp][3]);
        }
    }
    __syncthreads();   // all A reads done; reuse as C

#pragma unroll
    for (int jj = 0; jj < 4; ++jj)
#pragma unroll
        for (int pp = 0; pp < 8; ++pp)
            C[(4 * ty + jj) * 131 + tx + 16 * pp] = hsum1(acc[pp][jj]);
    __syncthreads();

    for (int i = tid; i < 8192; i += 256) {
        int j = i >> 7, px = i & 127;
        out[base + ((size_t)j << 16) + n0 + px] = C[j * 131 + px] + sBl[j];
    }
}

// ---------------------------------------------------------------------------
extern "C" void kernel_launch(void* const* d_in, const int* in_sizes, int n_in,
                              void* d_out, int out_size) {
    const float* x    = (const float*)d_in[0];
    const float* wqkv = (const float*)d_in[1];
    const float* bqkv = (const float*)d_in[2];
    const float* wln  = (const float*)d_in[3];
    const float* bln  = (const float*)d_in[4];
    float* out = (float*)d_out;

    cudaFuncSetAttribute(essa_qkv, cudaFuncAttributeMaxDynamicSharedMemorySize, 86528);
    cudaFuncSetAttribute(essa_out, cudaFuncAttributeMaxDynamicSharedMemorySize, 101632);

    dim3 gridQ(NPIX / 128, NBAT);
    essa_qkv<<<gridQ, 256, 86528>>>(x, wqkv, bqkv);

    dim3 gridM(NPIX / 512, NBAT);
    essa_kvacc<<<gridM, 256>>>();

    essa_wcat<<<NBAT, 256>>>(wln);

    essa_out<<<gridQ, 256, 101632>>>(bln, out);
}

// round 9
// speedup vs baseline: 1.4263x; 1.0793x over previous
#include <cuda_runtime.h>
#include <cstdint>

// ESSAttn: b=8, C=64, H=W=256, N=65536
// x, out: [b][C][N]  (b<<22 | c<<16 | n)
// scratch q2n,k2d,v: [b][N][C]  (b<<22 | n<<6 | c)

#define NPIX 65536
#define NBAT 8

typedef unsigned long long u64;

// ---------------- scratch ----------------
__device__ float g_q2n[(size_t)NBAT * 64 * NPIX];
__device__ float g_k2d[(size_t)NBAT * 64 * NPIX];
__device__ float g_v  [(size_t)NBAT * 64 * NPIX];
__device__ float g_M  [NBAT * 64 * 64];
__device__ float g_css[NBAT * 64];
__device__ float g_Wcat[NBAT * 64 * 128];   // [b][j][ 0..63: wln | 64..127: WK/256 ]

// ---------------- packed fp32 + async helpers ----------------
__device__ __forceinline__ u64 ffma2(u64 a, u64 b, u64 c) {
    u64 d;
    asm("fma.rn.f32x2 %0, %1, %2, %3;" : "=l"(d) : "l"(a), "l"(b), "l"(c));
    return d;
}
__device__ __forceinline__ u64 fadd2(u64 a, u64 b) {
    u64 d;
    asm("add.rn.f32x2 %0, %1, %2;" : "=l"(d) : "l"(a), "l"(b));
    return d;
}
__device__ __forceinline__ float2 unpack2(u64 v) {
    float lo, hi;
    asm("mov.b64 {%0, %1}, %2;" : "=f"(lo), "=f"(hi) : "l"(v));
    return make_float2(lo, hi);
}
__device__ __forceinline__ float hsum1(u64 v) {
    float2 r = unpack2(v);
    return r.x + r.y;
}
__device__ __forceinline__ float hsum2(u64 a, u64 b) {
    float2 r = unpack2(fadd2(a, b));
    return r.x + r.y;
}
__device__ __forceinline__ u64 lds_u64(const float* p) {
    return *reinterpret_cast<const u64*>(p);
}
__device__ __forceinline__ ulonglong2 lds_u128(const float* p) {
    return *reinterpret_cast<const ulonglong2*>(p);
}
__device__ __forceinline__ uint32_t smem_u32(const void* p) {
    uint32_t a;
    asm("{ .reg .u64 t; cvta.to.shared.u64 t, %1; cvt.u32.u64 %0, t; }" : "=r"(a) : "l"(p));
    return a;
}
__device__ __forceinline__ void cpa16(uint32_t dst, const float* src) {
    asm volatile("cp.async.cg.shared.global [%0], [%1], 16;" :: "r"(dst), "l"(src));
}
#define CPA_COMMIT() asm volatile("cp.async.commit_group;" ::: "memory")
#define CPA_WAIT(n)  asm volatile("cp.async.wait_group %0;" :: "n"(n) : "memory")

// ---------------------------------------------------------------------------
// GEMM pass core: acc[8][4] += A[128x68-pad] x Wp[64x68-pad], K=64
__device__ __forceinline__ void gemm64_pass(const float* __restrict__ A,
                                            const float* __restrict__ Wp,
                                            int tx, int ty, u64 acc[8][4]) {
#pragma unroll
    for (int pp = 0; pp < 8; ++pp)
#pragma unroll
        for (int jj = 0; jj < 4; ++jj) acc[pp][jj] = 0;
#pragma unroll 4
    for (int k4 = 0; k4 < 16; ++k4) {
        ulonglong2 b0 = lds_u128(Wp + (4 * ty + 0) * 68 + 4 * k4);
        ulonglong2 b1 = lds_u128(Wp + (4 * ty + 1) * 68 + 4 * k4);
        ulonglong2 b2 = lds_u128(Wp + (4 * ty + 2) * 68 + 4 * k4);
        ulonglong2 b3 = lds_u128(Wp + (4 * ty + 3) * 68 + 4 * k4);
#pragma unroll
        for (int pp = 0; pp < 8; ++pp) {
            ulonglong2 a = lds_u128(A + (tx + 16 * pp) * 68 + 4 * k4);
            acc[pp][0] = ffma2(a.x, b0.x, acc[pp][0]);
            acc[pp][0] = ffma2(a.y, b0.y, acc[pp][0]);
            acc[pp][1] = ffma2(a.x, b1.x, acc[pp][1]);
            acc[pp][1] = ffma2(a.y, b1.y, acc[pp][1]);
            acc[pp][2] = ffma2(a.x, b2.x, acc[pp][2]);
            acc[pp][2] = ffma2(a.y, b2.y, acc[pp][2]);
            acc[pp][3] = ffma2(a.x, b3.x, acc[pp][3]);
            acc[pp][3] = ffma2(a.y, b3.y, acc[pp][3]);
        }
    }
}

// ---------------------------------------------------------------------------
// qkv: per CTA 128 px, 3 passes of 64 outputs, double-buffered W via cp.async.
// smem floats: A[128*68]=8704 | Wp0 4352 | Wp1 4352 | C[64*131]=8384 | sB 192
__global__ __launch_bounds__(256, 2) void essa_qkv(const float* __restrict__ x,
                                                   const float* __restrict__ wqkv,
                                                   const float* __restrict__ bqkv) {
    extern __shared__ float sm[];
    float* A   = sm;
    float* Wp0 = sm + 8704;
    float* Wp1 = sm + 13056;
    float* C   = sm + 17408;
    float* sB  = sm + 25792;        // total 25984 fl = 103936 B

    const int tid = threadIdx.x;
    const int tx = tid & 15, ty = tid >> 4;
    const int b = blockIdx.y;
    const int n0 = blockIdx.x << 7;
    const size_t xbase = (size_t)b << 22;
    const uint32_t w0_32 = smem_u32(Wp0), w1_32 = smem_u32(Wp1);

    if (blockIdx.x == 0 && b == 0) {
        for (int i = tid; i < NBAT * 64 * 64; i += 256) g_M[i] = 0.f;
        for (int i = tid; i < NBAT * 64; i += 256) g_css[i] = 0.f;
    }

    // G0: Q weights -> Wp0 ; G1: K weights -> Wp1
    for (int i = tid; i < 1024; i += 256) {
        int j = i >> 4, ck = (i & 15) << 2;
        cpa16(w0_32 + (j * 68 + ck) * 4, wqkv + j * 64 + ck);
    }
    CPA_COMMIT();
    for (int i = tid; i < 1024; i += 256) {
        int j = i >> 4, ck = (i & 15) << 2;
        cpa16(w1_32 + (j * 68 + ck) * 4, wqkv + 4096 + j * 64 + ck);
    }
    CPA_COMMIT();

    // A transpose (x is [c][n]) + bias
    for (int i = tid; i < 8192; i += 256) {
        int k = i >> 7, px = i & 127;
        A[px * 68 + k] = x[xbase + ((size_t)k << 16) + n0 + px];
    }
    if (tid < 192) sB[tid] = bqkv[tid];
    CPA_WAIT(1);
    __syncthreads();

    const int lane = tid & 31, w = tid >> 5;
    const int spx = (w << 4) + (lane >> 1);
    const int h = lane & 1;

    u64 acc[8][4];

#pragma unroll 1
    for (int pass = 0; pass < 3; ++pass) {
        const float* Wp = (pass == 1) ? Wp1 : Wp0;
        gemm64_pass(A, Wp, tx, ty, acc);

        if (pass < 2) {
            __syncthreads();
#pragma unroll
            for (int jj = 0; jj < 4; ++jj)
#pragma unroll
                for (int pp = 0; pp < 8; ++pp)
                    C[(4 * ty + jj) * 131 + tx + 16 * pp] = hsum1(acc[pp][jj]);
            __syncthreads();

            if (pass == 0) {
                // G2: V weights -> Wp0 (Wp0 fully consumed)
                for (int i = tid; i < 1024; i += 256) {
                    int j = i >> 4, ck = (i & 15) << 2;
                    cpa16(w0_32 + (j * 68 + ck) * 4, wqkv + 8192 + j * 64 + ck);
                }
                CPA_COMMIT();
            }
            // stats: 2 threads per pixel
            {
                const int boff = pass * 64, j0 = h << 5;
                const size_t rownc = xbase + ((size_t)(n0 + spx) << 6);
                float rv[32];
                float part = 0.f;
#pragma unroll
                for (int t = 0; t < 32; ++t) {
                    rv[t] = C[(j0 + t) * 131 + spx] + sB[boff + j0 + t];
                    part += rv[t];
                }
                float mean = (part + __shfl_xor_sync(0xFFFFFFFFu, part, 1)) * (1.f / 64.f);
                float ss = 0.f;
#pragma unroll
                for (int t = 0; t < 32; ++t) {
                    float u = rv[t] - mean;
                    u = u * u;
                    rv[t] = u;
                    ss += u;
                }
                ss += __shfl_xor_sync(0xFFFFFFFFu, ss, 1);
                float inv = 1.f / (ss + 1e-7f);
                float scale;
                if (pass == 0) {
                    float nr = 0.f;
#pragma unroll
                    for (int t = 0; t < 32; ++t) {
                        float u = rv[t] * inv;
                        nr = fmaf(u, u, nr);
                    }
                    nr += __shfl_xor_sync(0xFFFFFFFFu, nr, 1);
                    scale = inv / fmaxf(sqrtf(nr), 1e-12f);
                } else {
                    scale = inv;
                }
                float* dst = (pass == 0 ? g_q2n : g_k2d) + rownc + j0;
#pragma unroll
                for (int t = 0; t < 8; ++t)
                    reinterpret_cast<float4*>(dst)[t] =
                        make_float4(rv[4 * t] * scale, rv[4 * t + 1] * scale,
                                    rv[4 * t + 2] * scale, rv[4 * t + 3] * scale);
            }
            if (pass == 0) { CPA_WAIT(1); } else { CPA_WAIT(0); }
            __syncthreads();
        } else {
            // V: direct register -> global
#pragma unroll
            for (int pp = 0; pp < 8; ++pp) {
                const int n = n0 + tx + 16 * pp;
                float4 v4 = make_float4(hsum1(acc[pp][0]) + sB[128 + 4 * ty + 0],
                                        hsum1(acc[pp][1]) + sB[128 + 4 * ty + 1],
                                        hsum1(acc[pp][2]) + sB[128 + 4 * ty + 2],
                                        hsum1(acc[pp][3]) + sB[128 + 4 * ty + 3]);
                *reinterpret_cast<float4*>(g_v + xbase + ((size_t)n << 6) + 4 * ty) = v4;
            }
        }
    }
}

// ---------------------------------------------------------------------------
// kvacc: M[c][d] += sum_n k2d[n][c]*v[n][d]; css[c] += sum k2d^2 (reg prefetch)
__global__ __launch_bounds__(256) void essa_kvacc() {
    const int b = blockIdx.y;
    const int n0 = blockIdx.x << 9;
    const size_t base = (size_t)b << 22;

    __shared__ float ks[64 * 33];                  // [c][nn]
    __shared__ __align__(16) float vs[32 * 68];    // [nn][d]

    const int tid = threadIdx.x;
    const int ty = tid >> 4, tx = tid & 15;
    const int c0 = ty << 2, d0 = tx << 2;

    // two load slots per thread: i0 = tid, i1 = tid + 256
    const int nnA = tid >> 4, c4A = (tid & 15) << 2;
    const int i1 = tid + 256;
    const int nnB = i1 >> 4, c4B = (i1 & 15) << 2;

    u64 acc[4][2];
#pragma unroll
    for (int i = 0; i < 4; ++i) { acc[i][0] = 0; acc[i][1] = 0; }
    float cssr = 0.f;

    // prefetch tile 0
    float4 ka, va, kb, vb;
    {
        size_t gA = base + ((size_t)(n0 + nnA) << 6) + c4A;
        size_t gB = base + ((size_t)(n0 + nnB) << 6) + c4B;
        ka = *reinterpret_cast<const float4*>(g_k2d + gA);
        va = *reinterpret_cast<const float4*>(g_v + gA);
        kb = *reinterpret_cast<const float4*>(g_k2d + gB);
        vb = *reinterpret_cast<const float4*>(g_v + gB);
    }

#pragma unroll 1
    for (int t = 0; t < 16; ++t) {
        __syncthreads();   // previous compute done
        ks[(c4A + 0) * 33 + nnA] = ka.x;
        ks[(c4A + 1) * 33 + nnA] = ka.y;
        ks[(c4A + 2) * 33 + nnA] = ka.z;
        ks[(c4A + 3) * 33 + nnA] = ka.w;
        *reinterpret_cast<float4*>(vs + nnA * 68 + c4A) = va;
        ks[(c4B + 0) * 33 + nnB] = kb.x;
        ks[(c4B + 1) * 33 + nnB] = kb.y;
        ks[(c4B + 2) * 33 + nnB] = kb.z;
        ks[(c4B + 3) * 33 + nnB] = kb.w;
        *reinterpret_cast<float4*>(vs + nnB * 68 + c4B) = vb;
        if (t < 15) {
            const int nb = n0 + ((t + 1) << 5);
            size_t gA = base + ((size_t)(nb + nnA) << 6) + c4A;
            size_t gB = base + ((size_t)(nb + nnB) << 6) + c4B;
            ka = *reinterpret_cast<const float4*>(g_k2d + gA);
            va = *reinterpret_cast<const float4*>(g_v + gA);
            kb = *reinterpret_cast<const float4*>(g_k2d + gB);
            vb = *reinterpret_cast<const float4*>(g_v + gB);
        }
        __syncthreads();
        const float* kp = ks + c0 * 33;
#pragma unroll 4
        for (int nn = 0; nn < 32; ++nn) {
            ulonglong2 v01 = *reinterpret_cast<const ulonglong2*>(vs + nn * 68 + d0);
            float k0 = kp[nn], k1 = kp[33 + nn], k2 = kp[66 + nn], k3 = kp[99 + nn];
            u64 kk0, kk1, kk2, kk3;
            asm("mov.b64 %0, {%1, %1};" : "=l"(kk0) : "f"(k0));
            asm("mov.b64 %0, {%1, %1};" : "=l"(kk1) : "f"(k1));
            asm("mov.b64 %0, {%1, %1};" : "=l"(kk2) : "f"(k2));
            asm("mov.b64 %0, {%1, %1};" : "=l"(kk3) : "f"(k3));
            acc[0][0] = ffma2(kk0, v01.x, acc[0][0]); acc[0][1] = ffma2(kk0, v01.y, acc[0][1]);
            acc[1][0] = ffma2(kk1, v01.x, acc[1][0]); acc[1][1] = ffma2(kk1, v01.y, acc[1][1]);
            acc[2][0] = ffma2(kk2, v01.x, acc[2][0]); acc[2][1] = ffma2(kk2, v01.y, acc[2][1]);
            acc[3][0] = ffma2(kk3, v01.x, acc[3][0]); acc[3][1] = ffma2(kk3, v01.y, acc[3][1]);
        }
        if (tid < 64) {
            const float* cp = ks + tid * 33;
#pragma unroll 8
            for (int nn = 0; nn < 32; ++nn) { float u = cp[nn]; cssr = fmaf(u, u, cssr); }
        }
    }

    float* Mp = g_M + (b << 12);
#pragma unroll
    for (int i = 0; i < 4; ++i) {
        float2 a0 = unpack2(acc[i][0]), a1 = unpack2(acc[i][1]);
        atomicAdd(&Mp[(c0 + i) * 64 + d0 + 0], a0.x);
        atomicAdd(&Mp[(c0 + i) * 64 + d0 + 1], a0.y);
        atomicAdd(&Mp[(c0 + i) * 64 + d0 + 2], a1.x);
        atomicAdd(&Mp[(c0 + i) * 64 + d0 + 3], a1.y);
    }
    if (tid < 64) atomicAdd(&g_css[(b << 6) + tid], cssr);
}

// ---------------------------------------------------------------------------
// wcat: Wcat[b][j][0..63] = wln[j][:];  Wcat[b][j][64+c] = (sum_d M[c][d]*wln[j][d]) / (nrm_c*256)
__global__ void essa_wcat(const float* __restrict__ wln) {
    __shared__ float sM[4096], sW[4096], sInv[64];
    const int b = blockIdx.x;
    const int tid = threadIdx.x;

    for (int i = tid; i < 4096; i += 256) {
        sM[i] = g_M[(b << 12) + i];
        sW[i] = wln[i];
    }
    if (tid < 64)
        sInv[tid] = 1.f / (fmaxf(sqrtf(g_css[(b << 6) + tid]), 1e-12f) * 256.f);
    __syncthreads();

    float* Wc = g_Wcat + (b << 13);
    for (int i = tid; i < 4096; i += 256) {
        int j = i >> 6, d = i & 63;
        Wc[j * 128 + d] = sW[i];
    }
#pragma unroll 1
    for (int t = 0; t < 16; ++t) {
        int i = tid + (t << 8);
        int j = i >> 6, c = i & 63;
        u64 s0 = 0, s1 = 0;
#pragma unroll
        for (int dd = 0; dd < 16; ++dd) {
            s0 = ffma2(lds_u64(sM + c * 64 + 4 * dd),     lds_u64(sW + j * 64 + 4 * dd),     s0);
            s1 = ffma2(lds_u64(sM + c * 64 + 4 * dd + 2), lds_u64(sW + j * 64 + 4 * dd + 2), s1);
        }
        Wc[j * 128 + 64 + c] = hsum2(s0, s1) * sInv[c];
    }
}

// ---------------------------------------------------------------------------
// out: K=128 GEMM out[n][j] = [v|q2n][n][:] . Wcat[b][j][:] + bln[j]
// cp.async K-split pipeline. smem: A[128*132] | Wc[64*132] | sBl[64]; C reuses A.
__global__ __launch_bounds__(256, 2) void essa_out(const float* __restrict__ bln,
                                                   float* __restrict__ out) {
    extern __shared__ float sm[];
    float* A   = sm;                 // 16896
    float* Wc  = sm + 16896;         // 8448
    float* sBl = sm + 25344;         // 64
    float* C   = sm;                 // reuse

    const int tid = threadIdx.x;
    const int tx = tid & 15, ty = tid >> 4;
    const int b = blockIdx.y;
    const int n0 = blockIdx.x << 7;
    const size_t base = (size_t)b << 22;
    const uint32_t A32 = smem_u32(A), Wc32 = smem_u32(Wc), B32 = smem_u32(sBl);
    const float* Wsrc = g_Wcat + (b << 13);

    // G0: v -> A[:,0:64], Wc lo, bias
    for (int i = tid; i < 2048; i += 256) {
        int px = i >> 4, ck = (i & 15) << 2;
        cpa16(A32 + (px * 132 + ck) * 4, g_v + base + ((size_t)(n0 + px) << 6) + ck);
    }
    for (int i = tid; i < 1024; i += 256) {
        int j = i >> 4, ck = (i & 15) << 2;
        cpa16(Wc32 + (j * 132 + ck) * 4, Wsrc + j * 128 + ck);
    }
    if (tid < 16) cpa16(B32 + tid * 16, bln + tid * 4);
    CPA_COMMIT();
    // G1: q2n -> A[:,64:128], Wc hi
    for (int i = tid; i < 2048; i += 256) {
        int px = i >> 4, ck = (i & 15) << 2;
        cpa16(A32 + (px * 132 + 64 + ck) * 4, g_q2n + base + ((size_t)(n0 + px) << 6) + ck);
    }
    for (int i = tid; i < 1024; i += 256) {
        int j = i >> 4, ck = (i & 15) << 2;
        cpa16(Wc32 + (j * 132 + 64 + ck) * 4, Wsrc + j * 128 + 64 + ck);
    }
    CPA_COMMIT();

    u64 acc[8][4];
#pragma unroll
    for (int pp = 0; pp < 8; ++pp)
#pragma unroll
        for (int jj = 0; jj < 4; ++jj) acc[pp][jj] = 0;

    CPA_WAIT(1);
    __syncthreads();

#pragma unroll 4
    for (int k4 = 0; k4 < 16; ++k4) {
        ulonglong2 b0 = lds_u128(Wc + (4 * ty + 0) * 132 + 4 * k4);
        ulonglong2 b1 = lds_u128(Wc + (4 * ty + 1) * 132 + 4 * k4);
        ulonglong2 b2 = lds_u128(Wc + (4 * ty + 2) * 132 + 4 * k4);
        ulonglong2 b3 = lds_u128(Wc + (4 * ty + 3) * 132 + 4 * k4);
#pragma unroll
        for (int pp = 0; pp < 8; ++pp) {
            ulonglong2 a = lds_u128(A + (tx + 16 * pp) * 132 + 4 * k4);
            acc[pp][0] = ffma2(a.x, b0.x, acc[pp][0]);
            acc[pp][0] = ffma2(a.y, b0.y, acc[pp][0]);
            acc[pp][1] = ffma2(a.x, b1.x, acc[pp][1]);
            acc[pp][1] = ffma2(a.y, b1.y, acc[pp][1]);
            acc[pp][2] = ffma2(a.x, b2.x, acc[pp][2]);
            acc[pp][2] = ffma2(a.y, b2.y, acc[pp][2]);
            acc[pp][3] = ffma2(a.x, b3.x, acc[pp][3]);
            acc[pp][3] = ffma2(a.y, b3.y, acc[pp][3]);
        }
    }
    CPA_WAIT(0);
    __syncthreads();
#pragma unroll 4
    for (int k4 = 16; k4 < 32; ++k4) {
        ulonglong2 b0 = lds_u128(Wc + (4 * ty + 0) * 132 + 4 * k4);
        ulonglong2 b1 = lds_u128(Wc + (4 * ty + 1) * 132 + 4 * k4);
        ulonglong2 b2 = lds_u128(Wc + (4 * ty + 2) * 132 + 4 * k4);
        ulonglong2 b3 = lds_u128(Wc + (4 * ty + 3) * 132 + 4 * k4);
#pragma unroll
        for (int pp = 0; pp < 8; ++pp) {
            ulonglong2 a = lds_u128(A + (tx + 16 * pp) * 132 + 4 * k4);
            acc[pp][0] = ffma2(a.x, b0.x, acc[pp][0]);
            acc[pp][0] = ffma2(a.y, b0.y, acc[pp][0]);
            acc[pp][1] = ffma2(a.x, b1.x, acc[pp][1]);
            acc[pp][1] = ffma2(a.y, b1.y, acc[pp][1]);
            acc[pp][2] = ffma2(a.x, b2.x, acc[pp][2]);
            acc[pp][2] = ffma2(a.y, b2.y, acc[pp][2]);
            acc[pp][3] = ffma2(a.x, b3.x, acc[pp][3]);
            acc[pp][3] = ffma2(a.y, b3.y, acc[pp][3]);
        }
    }
    __syncthreads();   // all A reads done; reuse as C

#pragma unroll
    for (int jj = 0; jj < 4; ++jj)
#pragma unroll
        for (int pp = 0; pp < 8; ++pp)
            C[(4 * ty + jj) * 131 + tx + 16 * pp] = hsum1(acc[pp][jj]);
    __syncthreads();

    for (int i = tid; i < 8192; i += 256) {
        int j = i >> 7, px = i & 127;
        out[base + ((size_t)j << 16) + n0 + px] = C[j * 131 + px] + sBl[j];
    }
}

// ---------------------------------------------------------------------------
extern "C" void kernel_launch(void* const* d_in, const int* in_sizes, int n_in,
                              void* d_out, int out_size) {
    const float* x    = (const float*)d_in[0];
    const float* wqkv = (const float*)d_in[1];
    const float* bqkv = (const float*)d_in[2];
    const float* wln  = (const float*)d_in[3];
    const float* bln  = (const float*)d_in[4];
    float* out = (float*)d_out;

    cudaFuncSetAttribute(essa_qkv, cudaFuncAttributeMaxDynamicSharedMemorySize, 103936);
    cudaFuncSetAttribute(essa_out, cudaFuncAttributeMaxDynamicSharedMemorySize, 101632);

    dim3 gridQ(NPIX / 128, NBAT);
    essa_qkv<<<gridQ, 256, 103936>>>(x, wqkv, bqkv);

    dim3 gridM(NPIX / 512, NBAT);
    essa_kvacc<<<gridM, 256>>>();

    essa_wcat<<<NBAT, 256>>>(wln);

    essa_out<<<gridQ, 256, 101632>>>(bln, out);
}

// round 11
// speedup vs baseline: 1.5831x; 1.1099x over previous
#include <cuda_runtime.h>
#include <cstdint>

// ESSAttn: b=8, C=64, H=W=256, N=65536
// x, out: [b][C][N]  (b<<22 | c<<16 | n)
// scratch q2n,k2d,v: [b][N][C]  (b<<22 | n<<6 | c)

#define NPIX 65536
#define NBAT 8

typedef unsigned long long u64;

// ---------------- scratch ----------------
__device__ float g_q2n[(size_t)NBAT * 64 * NPIX];
__device__ float g_k2d[(size_t)NBAT * 64 * NPIX];
__device__ float g_v  [(size_t)NBAT * 64 * NPIX];
__device__ float g_M  [NBAT * 64 * 64];
__device__ float g_css[NBAT * 64];
__device__ float g_WcT[NBAT * 128 * 64];   // [b][k][j]  k-major concat weight

// ---------------- packed fp32 + async helpers ----------------
__device__ __forceinline__ u64 ffma2(u64 a, u64 b, u64 c) {
    u64 d;
    asm("fma.rn.f32x2 %0, %1, %2, %3;" : "=l"(d) : "l"(a), "l"(b), "l"(c));
    return d;
}
__device__ __forceinline__ u64 fadd2(u64 a, u64 b) {
    u64 d;
    asm("add.rn.f32x2 %0, %1, %2;" : "=l"(d) : "l"(a), "l"(b));
    return d;
}
__device__ __forceinline__ float2 unpack2(u64 v) {
    float lo, hi;
    asm("mov.b64 {%0, %1}, %2;" : "=f"(lo), "=f"(hi) : "l"(v));
    return make_float2(lo, hi);
}
__device__ __forceinline__ u64 dup2(float f) {
    u64 d;
    asm("mov.b64 %0, {%1, %1};" : "=l"(d) : "f"(f));
    return d;
}
__device__ __forceinline__ float hsum2(u64 a, u64 b) {
    float2 r = unpack2(fadd2(a, b));
    return r.x + r.y;
}
__device__ __forceinline__ u64 lds_u64(const float* p) {
    return *reinterpret_cast<const u64*>(p);
}
__device__ __forceinline__ ulonglong2 lds_u128(const float* p) {
    return *reinterpret_cast<const ulonglong2*>(p);
}
__device__ __forceinline__ uint32_t smem_u32(const void* p) {
    uint32_t a;
    asm("{ .reg .u64 t; cvta.to.shared.u64 t, %1; cvt.u32.u64 %0, t; }" : "=r"(a) : "l"(p));
    return a;
}
__device__ __forceinline__ void cpa16(uint32_t dst, const float* src) {
    asm volatile("cp.async.cg.shared.global [%0], [%1], 16;" :: "r"(dst), "l"(src));
}
#define CPA_COMMIT() asm volatile("cp.async.commit_group;" ::: "memory")
#define CPA_WAIT(n)  asm volatile("cp.async.wait_group %0;" :: "n"(n) : "memory")

// ---------------------------------------------------------------------------
// qkv GEMM core (px-packing): acc[pq][jj] u64 = (out(px0), out(px0+1)),
// px0 = 2*(tx+16*pq), j = 8*ty+jj.  A[k][px] pad 132, W[j][k] rows of 64.
__device__ __forceinline__ void gemm_px(const float* __restrict__ A,
                                        const float* __restrict__ W,
                                        int tx, int ty, u64 acc[4][8]) {
#pragma unroll
    for (int pq = 0; pq < 4; ++pq)
#pragma unroll
        for (int jj = 0; jj < 8; ++jj) acc[pq][jj] = 0;
#pragma unroll 2
    for (int k4 = 0; k4 < 16; ++k4) {
        u64 av[4][4];   // [kk][pq]
#pragma unroll
        for (int kk = 0; kk < 4; ++kk)
#pragma unroll
            for (int pq = 0; pq < 4; ++pq)
                av[kk][pq] = lds_u64(A + (4 * k4 + kk) * 132 + 2 * (tx + 16 * pq));
#pragma unroll
        for (int jj = 0; jj < 8; ++jj) {
            ulonglong2 bb = lds_u128(W + (8 * ty + jj) * 64 + 4 * k4);
            float2 bl = unpack2(bb.x), bh = unpack2(bb.y);
            u64 d0 = dup2(bl.x), d1 = dup2(bl.y), d2 = dup2(bh.x), d3 = dup2(bh.y);
#pragma unroll
            for (int pq = 0; pq < 4; ++pq) {
                acc[pq][jj] = ffma2(av[0][pq], d0, acc[pq][jj]);
                acc[pq][jj] = ffma2(av[1][pq], d1, acc[pq][jj]);
                acc[pq][jj] = ffma2(av[2][pq], d2, acc[pq][jj]);
                acc[pq][jj] = ffma2(av[3][pq], d3, acc[pq][jj]);
            }
        }
    }
}

// ---------------------------------------------------------------------------
// qkv: 128 thr/CTA, 128 px, 3 passes of 64 outputs.
// smem fl: A[64*132]=8448 | W0 4096 | W1 4096 | C[64*130]=8320 | sB 192  -> 100608 B
__global__ __launch_bounds__(128) void essa_qkv(const float* __restrict__ x,
                                                const float* __restrict__ wqkv,
                                                const float* __restrict__ bqkv) {
    extern __shared__ float sm[];
    float* A  = sm;
    float* W0 = sm + 8448;
    float* W1 = sm + 12544;
    float* C  = sm + 16640;
    float* sB = sm + 24960;

    const int tid = threadIdx.x;
    const int tx = tid & 15, ty = tid >> 4;
    const int b = blockIdx.y;
    const int n0 = blockIdx.x << 7;
    const size_t base = (size_t)b << 22;
    const uint32_t A32 = smem_u32(A), W032 = smem_u32(W0), W132 = smem_u32(W1);

    if (blockIdx.x == 0 && b == 0) {
        for (int i = tid; i < NBAT * 64 * 64; i += 128) g_M[i] = 0.f;
        for (int i = tid; i < NBAT * 64; i += 128) g_css[i] = 0.f;
    }

    // G0: A rows (row copy from x [c][n]; FULL tile: 64 rows x 32 chunks) + W(Q)
    for (int i = tid; i < 2048; i += 128) {
        int k = i >> 5, ck = (i & 31) << 2;
        cpa16(A32 + (k * 132 + ck) * 4, x + base + ((size_t)k << 16) + n0 + ck);
    }
    for (int i = tid; i < 1024; i += 128) {
        int j = i >> 4, ck = (i & 15) << 2;
        cpa16(W032 + (j * 64 + ck) * 4, wqkv + j * 64 + ck);
    }
    CPA_COMMIT();
    // G1: W(K)
    for (int i = tid; i < 1024; i += 128) {
        int j = i >> 4, ck = (i & 15) << 2;
        cpa16(W132 + (j * 64 + ck) * 4, wqkv + 4096 + j * 64 + ck);
    }
    CPA_COMMIT();
    if (tid < 48) *(float4*)(sB + tid * 4) = *(const float4*)(bqkv + tid * 4);
    CPA_WAIT(1);
    __syncthreads();

    u64 acc[4][8];

#pragma unroll 1
    for (int pass = 0; pass < 3; ++pass) {
        gemm_px(A, (pass == 1) ? W1 : W0, tx, ty, acc);

        if (pass < 2) {
            __syncthreads();   // all warps done reading current W buffer
            if (pass == 0) {   // V weights -> W0
                for (int i = tid; i < 1024; i += 128) {
                    int j = i >> 4, ck = (i & 15) << 2;
                    cpa16(W032 + (j * 64 + ck) * 4, wqkv + 8192 + j * 64 + ck);
                }
                CPA_COMMIT();
            }
            // stage C[j][px] pad 130 (STS.64)
#pragma unroll
            for (int jj = 0; jj < 8; ++jj)
#pragma unroll
                for (int pq = 0; pq < 4; ++pq)
                    *(u64*)(C + (8 * ty + jj) * 130 + 2 * (tx + 16 * pq)) = acc[pq][jj];
            __syncthreads();

            // stats: 1 thread per pixel
            {
                const int px = tid;
                const int boff = pass * 64;
                const size_t rownc = base + ((size_t)(n0 + px) << 6);
                float rv[64];
                float part = 0.f;
#pragma unroll 8
                for (int j = 0; j < 64; ++j) {
                    rv[j] = C[j * 130 + px] + sB[boff + j];
                    part += rv[j];
                }
                float mean = part * (1.f / 64.f);
                float ss = 0.f;
#pragma unroll 8
                for (int j = 0; j < 64; ++j) {
                    float u = rv[j] - mean;
                    u = u * u;
                    rv[j] = u;
                    ss += u;
                }
                float inv = 1.f / (ss + 1e-7f);
                float scale;
                if (pass == 0) {
                    float nr = 0.f;
#pragma unroll 8
                    for (int j = 0; j < 64; ++j) {
                        float u = rv[j] * inv;
                        nr = fmaf(u, u, nr);
                    }
                    scale = inv / fmaxf(sqrtf(nr), 1e-12f);
                } else {
                    scale = inv;
                }
                float* dst = (pass == 0 ? g_q2n : g_k2d) + rownc;
#pragma unroll
                for (int t = 0; t < 16; ++t)
                    reinterpret_cast<float4*>(dst)[t] =
                        make_float4(rv[4 * t] * scale, rv[4 * t + 1] * scale,
                                    rv[4 * t + 2] * scale, rv[4 * t + 3] * scale);
            }
            if (pass == 0) { CPA_WAIT(1); } else { CPA_WAIT(0); }
            __syncthreads();
        } else {
            // V: assemble float4 rows from packed acc and store to g_v [n][c]
            float bs[8];
#pragma unroll
            for (int jj = 0; jj < 8; ++jj) bs[jj] = sB[128 + 8 * ty + jj];
#pragma unroll
            for (int pq = 0; pq < 4; ++pq) {
                const int n = n0 + 2 * (tx + 16 * pq);
                float* dst = g_v + base + ((size_t)n << 6) + 8 * ty;
                float2 u0 = unpack2(acc[pq][0]), u1 = unpack2(acc[pq][1]);
                float2 u2 = unpack2(acc[pq][2]), u3 = unpack2(acc[pq][3]);
                float2 u4 = unpack2(acc[pq][4]), u5 = unpack2(acc[pq][5]);
                float2 u6 = unpack2(acc[pq][6]), u7 = unpack2(acc[pq][7]);
                *(float4*)(dst)      = make_float4(u0.x + bs[0], u1.x + bs[1], u2.x + bs[2], u3.x + bs[3]);
                *(float4*)(dst + 4)  = make_float4(u4.x + bs[4], u5.x + bs[5], u6.x + bs[6], u7.x + bs[7]);
                *(float4*)(dst + 64) = make_float4(u0.y + bs[0], u1.y + bs[1], u2.y + bs[2], u3.y + bs[3]);
                *(float4*)(dst + 68) = make_float4(u4.y + bs[4], u5.y + bs[5], u6.y + bs[6], u7.y + bs[7]);
            }
        }
    }
}

// ---------------------------------------------------------------------------
// kvacc: reg-prefetch, FFMA2 (unchanged)
__global__ __launch_bounds__(256) void essa_kvacc() {
    const int b = blockIdx.y;
    const int n0 = blockIdx.x << 9;
    const size_t base = (size_t)b << 22;

    __shared__ float ks[64 * 33];
    __shared__ __align__(16) float vs[32 * 68];

    const int tid = threadIdx.x;
    const int ty = tid >> 4, tx = tid & 15;
    const int c0 = ty << 2, d0 = tx << 2;

    const int nnA = tid >> 4, c4A = (tid & 15) << 2;
    const int i1 = tid + 256;
    const int nnB = i1 >> 4, c4B = (i1 & 15) << 2;

    u64 acc[4][2];
#pragma unroll
    for (int i = 0; i < 4; ++i) { acc[i][0] = 0; acc[i][1] = 0; }
    float cssr = 0.f;

    float4 ka, va, kb, vb;
    {
        size_t gA = base + ((size_t)(n0 + nnA) << 6) + c4A;
        size_t gB = base + ((size_t)(n0 + nnB) << 6) + c4B;
        ka = *reinterpret_cast<const float4*>(g_k2d + gA);
        va = *reinterpret_cast<const float4*>(g_v + gA);
        kb = *reinterpret_cast<const float4*>(g_k2d + gB);
        vb = *reinterpret_cast<const float4*>(g_v + gB);
    }

#pragma unroll 1
    for (int t = 0; t < 16; ++t) {
        __syncthreads();
        ks[(c4A + 0) * 33 + nnA] = ka.x;
        ks[(c4A + 1) * 33 + nnA] = ka.y;
        ks[(c4A + 2) * 33 + nnA] = ka.z;
        ks[(c4A + 3) * 33 + nnA] = ka.w;
        *reinterpret_cast<float4*>(vs + nnA * 68 + c4A) = va;
        ks[(c4B + 0) * 33 + nnB] = kb.x;
        ks[(c4B + 1) * 33 + nnB] = kb.y;
        ks[(c4B + 2) * 33 + nnB] = kb.z;
        ks[(c4B + 3) * 33 + nnB] = kb.w;
        *reinterpret_cast<float4*>(vs + nnB * 68 + c4B) = vb;
        if (t < 15) {
            const int nb = n0 + ((t + 1) << 5);
            size_t gA = base + ((size_t)(nb + nnA) << 6) + c4A;
            size_t gB = base + ((size_t)(nb + nnB) << 6) + c4B;
            ka = *reinterpret_cast<const float4*>(g_k2d + gA);
            va = *reinterpret_cast<const float4*>(g_v + gA);
            kb = *reinterpret_cast<const float4*>(g_k2d + gB);
            vb = *reinterpret_cast<const float4*>(g_v + gB);
        }
        __syncthreads();
        const float* kp = ks + c0 * 33;
#pragma unroll 4
        for (int nn = 0; nn < 32; ++nn) {
            ulonglong2 v01 = *reinterpret_cast<const ulonglong2*>(vs + nn * 68 + d0);
            float k0 = kp[nn], k1 = kp[33 + nn], k2 = kp[66 + nn], k3 = kp[99 + nn];
            u64 kk0 = dup2(k0), kk1 = dup2(k1), kk2 = dup2(k2), kk3 = dup2(k3);
            acc[0][0] = ffma2(kk0, v01.x, acc[0][0]); acc[0][1] = ffma2(kk0, v01.y, acc[0][1]);
            acc[1][0] = ffma2(kk1, v01.x, acc[1][0]); acc[1][1] = ffma2(kk1, v01.y, acc[1][1]);
            acc[2][0] = ffma2(kk2, v01.x, acc[2][0]); acc[2][1] = ffma2(kk2, v01.y, acc[2][1]);
            acc[3][0] = ffma2(kk3, v01.x, acc[3][0]); acc[3][1] = ffma2(kk3, v01.y, acc[3][1]);
        }
        if (tid < 64) {
            const float* cp = ks + tid * 33;
#pragma unroll 8
            for (int nn = 0; nn < 32; ++nn) { float u = cp[nn]; cssr = fmaf(u, u, cssr); }
        }
    }

    float* Mp = g_M + (b << 12);
#pragma unroll
    for (int i = 0; i < 4; ++i) {
        float2 a0 = unpack2(acc[i][0]), a1 = unpack2(acc[i][1]);
        atomicAdd(&Mp[(c0 + i) * 64 + d0 + 0], a0.x);
        atomicAdd(&Mp[(c0 + i) * 64 + d0 + 1], a0.y);
        atomicAdd(&Mp[(c0 + i) * 64 + d0 + 2], a1.x);
        atomicAdd(&Mp[(c0 + i) * 64 + d0 + 3], a1.y);
    }
    if (tid < 64) atomicAdd(&g_css[(b << 6) + tid], cssr);
}

// ---------------------------------------------------------------------------
// wcat: emit k-major concat weight WcT[b][k][j]:
//   k<64:   WcT[k][j] = wln[j][k]
//   k=64+c: WcT[64+c][j] = (sum_d M[c][d]*wln[j][d]) / (nrm_c*256)
__global__ void essa_wcat(const float* __restrict__ wln) {
    __shared__ float sM[4096], sW[4096], sInv[64];
    const int b = blockIdx.x;
    const int tid = threadIdx.x;

    for (int i = tid; i < 4096; i += 256) {
        sM[i] = g_M[(b << 12) + i];
        sW[i] = wln[i];
    }
    if (tid < 64)
        sInv[tid] = 1.f / (fmaxf(sqrtf(g_css[(b << 6) + tid]), 1e-12f) * 256.f);
    __syncthreads();

    float* Wc = g_WcT + (b << 13);
    for (int i = tid; i < 4096; i += 256) {
        int k = i >> 6, j = i & 63;
        Wc[k * 64 + j] = sW[j * 64 + k];
    }
#pragma unroll 1
    for (int t = 0; t < 16; ++t) {
        int i = tid + (t << 8);
        int c = i >> 6, j = i & 63;
        u64 s0 = 0, s1 = 0;
#pragma unroll
        for (int dd = 0; dd < 16; ++dd) {
            s0 = ffma2(lds_u64(sM + c * 64 + 4 * dd),     lds_u64(sW + j * 64 + 4 * dd),     s0);
            s1 = ffma2(lds_u64(sM + c * 64 + 4 * dd + 2), lds_u64(sW + j * 64 + 4 * dd + 2), s1);
        }
        Wc[(64 + c) * 64 + j] = hsum2(s0, s1) * sInv[c];
    }
}

// ---------------------------------------------------------------------------
// out GEMM core (j-packing): acc[pp][jq] u64 = (out(px, j0), out(px, j0+1)),
// px = tx+16*pp, j0 = 8*ty+2*jq.  A[px][k] pad 132, Wt[k][j] rows of 64.
__device__ __forceinline__ void gemm_j(const float* __restrict__ A,
                                       const float* __restrict__ Wt,
                                       int tx, int ty, int k4lo, int k4hi,
                                       u64 acc[8][4]) {
#pragma unroll 2
    for (int k4 = k4lo; k4 < k4hi; ++k4) {
        ulonglong2 bt0[4], bt1[4];
#pragma unroll
        for (int kk = 0; kk < 4; ++kk) {
            bt0[kk] = lds_u128(Wt + (4 * k4 + kk) * 64 + 8 * ty);
            bt1[kk] = lds_u128(Wt + (4 * k4 + kk) * 64 + 8 * ty + 4);
        }
#pragma unroll
        for (int pp = 0; pp < 8; ++pp) {
            ulonglong2 a = lds_u128(A + (tx + 16 * pp) * 132 + 4 * k4);
            float2 al = unpack2(a.x), ah = unpack2(a.y);
            u64 d0 = dup2(al.x), d1 = dup2(al.y), d2 = dup2(ah.x), d3 = dup2(ah.y);
            acc[pp][0] = ffma2(d0, bt0[0].x, acc[pp][0]);
            acc[pp][1] = ffma2(d0, bt0[0].y, acc[pp][1]);
            acc[pp][2] = ffma2(d0, bt1[0].x, acc[pp][2]);
            acc[pp][3] = ffma2(d0, bt1[0].y, acc[pp][3]);
            acc[pp][0] = ffma2(d1, bt0[1].x, acc[pp][0]);
            acc[pp][1] = ffma2(d1, bt0[1].y, acc[pp][1]);
            acc[pp][2] = ffma2(d1, bt1[1].x, acc[pp][2]);
            acc[pp][3] = ffma2(d1, bt1[1].y, acc[pp][3]);
            acc[pp][0] = ffma2(d2, bt0[2].x, acc[pp][0]);
            acc[pp][1] = ffma2(d2, bt0[2].y, acc[pp][1]);
            acc[pp][2] = ffma2(d2, bt1[2].x, acc[pp][2]);
            acc[pp][3] = ffma2(d2, bt1[2].y, acc[pp][3]);
            acc[pp][0] = ffma2(d3, bt0[3].x, acc[pp][0]);
            acc[pp][1] = ffma2(d3, bt0[3].y, acc[pp][1]);
            acc[pp][2] = ffma2(d3, bt1[3].x, acc[pp][2]);
            acc[pp][3] = ffma2(d3, bt1[3].y, acc[pp][3]);
        }
    }
}

// ---------------------------------------------------------------------------
// out: K=128 GEMM out[n][j] = [v|q2n][n][:] . WcT[:][j] + bln[j]
// smem fl: A[128*132]=16896 | Wt[128*64]=8192 | sBl 64; C[128*66] overlays A
__global__ __launch_bounds__(128) void essa_out(const float* __restrict__ bln,
                                                float* __restrict__ out) {
    extern __shared__ float sm[];
    float* A   = sm;
    float* Wt  = sm + 16896;
    float* sBl = sm + 25088;
    float* C   = sm;   // overlay

    const int tid = threadIdx.x;
    const int tx = tid & 15, ty = tid >> 4;
    const int b = blockIdx.y;
    const int n0 = blockIdx.x << 7;
    const size_t base = (size_t)b << 22;
    const uint32_t A32 = smem_u32(A), Wt32 = smem_u32(Wt), B32 = smem_u32(sBl);
    const float* Ws = g_WcT + (b << 13);

    // G0: v -> A[:,0:64], Wt rows 0..63, bias
    for (int i = tid; i < 2048; i += 128) {
        int px = i >> 4, ck = (i & 15) << 2;
        cpa16(A32 + (px * 132 + ck) * 4, g_v + base + ((size_t)(n0 + px) << 6) + ck);
    }
    for (int i = tid; i < 1024; i += 128) {
        int k = i >> 4, ck = (i & 15) << 2;
        cpa16(Wt32 + (k * 64 + ck) * 4, Ws + k * 64 + ck);
    }
    if (tid < 16) cpa16(B32 + tid * 16, bln + tid * 4);
    CPA_COMMIT();
    // G1: q2n -> A[:,64:128], Wt rows 64..127
    for (int i = tid; i < 2048; i += 128) {
        int px = i >> 4, ck = (i & 15) << 2;
        cpa16(A32 + (px * 132 + 64 + ck) * 4, g_q2n + base + ((size_t)(n0 + px) << 6) + ck);
    }
    for (int i = tid; i < 1024; i += 128) {
        int k = i >> 4, ck = (i & 15) << 2;
        cpa16(Wt32 + ((64 + k) * 64 + ck) * 4, Ws + (64 + k) * 64 + ck);
    }
    CPA_COMMIT();

    u64 acc[8][4];
#pragma unroll
    for (int pp = 0; pp < 8; ++pp)
#pragma unroll
        for (int jq = 0; jq < 4; ++jq) acc[pp][jq] = 0;

    CPA_WAIT(1);
    __syncthreads();
    gemm_j(A, Wt, tx, ty, 0, 16, acc);
    CPA_WAIT(0);
    __syncthreads();
    gemm_j(A, Wt, tx, ty, 16, 32, acc);
    __syncthreads();   // A reads done -> C overlay

    // stage C[px][j] pad 66 (STS.64 of j-pairs)
#pragma unroll
    for (int pp = 0; pp < 8; ++pp)
#pragma unroll
        for (int jq = 0; jq < 4; ++jq)
            *(u64*)(C + (tx + 16 * pp) * 66 + 8 * ty + 2 * jq) = acc[pp][jq];
    __syncthreads();

    for (int i = tid; i < 8192; i += 128) {
        int j = i >> 7, px = i & 127;
        out[base + ((size_t)j << 16) + n0 + px] = C[px * 66 + j] + sBl[j];
    }
}

// ---------------------------------------------------------------------------
extern "C" void kernel_launch(void* const* d_in, const int* in_sizes, int n_in,
                              void* d_out, int out_size) {
    const float* x    = (const float*)d_in[0];
    const float* wqkv = (const float*)d_in[1];
    const float* bqkv = (const float*)d_in[2];
    const float* wln  = (const float*)d_in[3];
    const float* bln  = (const float*)d_in[4];
    float* out = (float*)d_out;

    cudaFuncSetAttribute(essa_qkv, cudaFuncAttributeMaxDynamicSharedMemorySize, 100608);
    cudaFuncSetAttribute(essa_out, cudaFuncAttributeMaxDynamicSharedMemorySize, 100608);

    dim3 gridQ(NPIX / 128, NBAT);
    essa_qkv<<<gridQ, 128, 100608>>>(x, wqkv, bqkv);

    dim3 gridM(NPIX / 512, NBAT);
    essa_kvacc<<<gridM, 256>>>();

    essa_wcat<<<NBAT, 256>>>(wln);

    essa_out<<<gridQ, 128, 100608>>>(bln, out);
}

// round 12
// speedup vs baseline: 1.5875x; 1.0028x over previous
#include <cuda_runtime.h>
#include <cstdint>

// ESSAttn: b=8, C=64, H=W=256, N=65536
// x, out: [b][C][N]  (b<<22 | c<<16 | n)
// scratch q2n,k2d,v: [b][N][C]  (b<<22 | n<<6 | c)

#define NPIX 65536
#define NBAT 8

typedef unsigned long long u64;

// ---------------- scratch ----------------
__device__ float g_q2n[(size_t)NBAT * 64 * NPIX];
__device__ float g_k2d[(size_t)NBAT * 64 * NPIX];
__device__ float g_v  [(size_t)NBAT * 64 * NPIX];
__device__ float g_M  [NBAT * 64 * 64];
__device__ float g_css[NBAT * 64];
__device__ float g_WcT[NBAT * 128 * 64];   // [b][k][j]  k-major concat weight

// ---------------- packed fp32 + async helpers ----------------
__device__ __forceinline__ u64 ffma2(u64 a, u64 b, u64 c) {
    u64 d;
    asm("fma.rn.f32x2 %0, %1, %2, %3;" : "=l"(d) : "l"(a), "l"(b), "l"(c));
    return d;
}
__device__ __forceinline__ u64 fadd2(u64 a, u64 b) {
    u64 d;
    asm("add.rn.f32x2 %0, %1, %2;" : "=l"(d) : "l"(a), "l"(b));
    return d;
}
__device__ __forceinline__ float2 unpack2(u64 v) {
    float lo, hi;
    asm("mov.b64 {%0, %1}, %2;" : "=f"(lo), "=f"(hi) : "l"(v));
    return make_float2(lo, hi);
}
__device__ __forceinline__ u64 dup2(float f) {
    u64 d;
    asm("mov.b64 %0, {%1, %1};" : "=l"(d) : "f"(f));
    return d;
}
__device__ __forceinline__ float hsum2(u64 a, u64 b) {
    float2 r = unpack2(fadd2(a, b));
    return r.x + r.y;
}
__device__ __forceinline__ u64 lds_u64(const float* p) {
    return *reinterpret_cast<const u64*>(p);
}
__device__ __forceinline__ ulonglong2 lds_u128(const float* p) {
    return *reinterpret_cast<const ulonglong2*>(p);
}
__device__ __forceinline__ uint32_t smem_u32(const void* p) {
    uint32_t a;
    asm("{ .reg .u64 t; cvta.to.shared.u64 t, %1; cvt.u32.u64 %0, t; }" : "=r"(a) : "l"(p));
    return a;
}
__device__ __forceinline__ void cpa16(uint32_t dst, const float* src) {
    asm volatile("cp.async.cg.shared.global [%0], [%1], 16;" :: "r"(dst), "l"(src));
}
#define CPA_COMMIT() asm volatile("cp.async.commit_group;" ::: "memory")
#define CPA_WAIT(n)  asm volatile("cp.async.wait_group %0;" :: "n"(n) : "memory")

// ---------------------------------------------------------------------------
// qkv GEMM core (256 thr, px-packing): tx=tid&31, ty=tid>>5 (warp==ty).
// acc[pq][jj] = (out(px0), out(px0+1)), px0 = 2*(tx+32*pq), j = 8*ty+jj.
// A[k][px] pad 132, W[j][k] rows of 64. B loads are whole-warp broadcasts.
__device__ __forceinline__ void gemm_px(const float* __restrict__ A,
                                        const float* __restrict__ W,
                                        int tx, int ty, u64 acc[2][8]) {
#pragma unroll
    for (int pq = 0; pq < 2; ++pq)
#pragma unroll
        for (int jj = 0; jj < 8; ++jj) acc[pq][jj] = 0;
#pragma unroll 2
    for (int k4 = 0; k4 < 16; ++k4) {
        u64 av[4][2];   // [kk][pq]
#pragma unroll
        for (int kk = 0; kk < 4; ++kk)
#pragma unroll
            for (int pq = 0; pq < 2; ++pq)
                av[kk][pq] = lds_u64(A + (4 * k4 + kk) * 132 + 2 * (tx + 32 * pq));
#pragma unroll
        for (int jj = 0; jj < 8; ++jj) {
            ulonglong2 bb = lds_u128(W + (8 * ty + jj) * 64 + 4 * k4);
            float2 bl = unpack2(bb.x), bh = unpack2(bb.y);
            u64 d0 = dup2(bl.x), d1 = dup2(bl.y), d2 = dup2(bh.x), d3 = dup2(bh.y);
#pragma unroll
            for (int pq = 0; pq < 2; ++pq) {
                acc[pq][jj] = ffma2(av[0][pq], d0, acc[pq][jj]);
                acc[pq][jj] = ffma2(av[1][pq], d1, acc[pq][jj]);
                acc[pq][jj] = ffma2(av[2][pq], d2, acc[pq][jj]);
                acc[pq][jj] = ffma2(av[3][pq], d3, acc[pq][jj]);
            }
        }
    }
}

// ---------------------------------------------------------------------------
// qkv: 256 thr/CTA, 128 px, 3 passes of 64 outputs.
// smem fl: A[64*132]=8448 | W0 4096 | W1 4096 | C[64*130]=8320 | sB 192 -> 100608 B
__global__ __launch_bounds__(256) void essa_qkv(const float* __restrict__ x,
                                                const float* __restrict__ wqkv,
                                                const float* __restrict__ bqkv) {
    extern __shared__ float sm[];
    float* A  = sm;
    float* W0 = sm + 8448;
    float* W1 = sm + 12544;
    float* C  = sm + 16640;
    float* sB = sm + 24960;

    const int tid = threadIdx.x;
    const int tx = tid & 31, ty = tid >> 5;
    const int b = blockIdx.y;
    const int n0 = blockIdx.x << 7;
    const size_t base = (size_t)b << 22;
    const uint32_t A32 = smem_u32(A), W032 = smem_u32(W0), W132 = smem_u32(W1);

    if (blockIdx.x == 0 && b == 0) {
        for (int i = tid; i < NBAT * 64 * 64; i += 256) g_M[i] = 0.f;
        for (int i = tid; i < NBAT * 64; i += 256) g_css[i] = 0.f;
    }

    // G0: A rows (row copy from x [c][n]; 64 rows x 32 chunks) + W(Q)
    for (int i = tid; i < 2048; i += 256) {
        int k = i >> 5, ck = (i & 31) << 2;
        cpa16(A32 + (k * 132 + ck) * 4, x + base + ((size_t)k << 16) + n0 + ck);
    }
    for (int i = tid; i < 1024; i += 256) {
        int j = i >> 4, ck = (i & 15) << 2;
        cpa16(W032 + (j * 64 + ck) * 4, wqkv + j * 64 + ck);
    }
    CPA_COMMIT();
    // G1: W(K)
    for (int i = tid; i < 1024; i += 256) {
        int j = i >> 4, ck = (i & 15) << 2;
        cpa16(W132 + (j * 64 + ck) * 4, wqkv + 4096 + j * 64 + ck);
    }
    CPA_COMMIT();
    if (tid < 48) *(float4*)(sB + tid * 4) = *(const float4*)(bqkv + tid * 4);
    CPA_WAIT(1);
    __syncthreads();

    // stats mapping: 2 threads per pixel (partner = tid^1, same warp)
    const int spx = tid >> 1;
    const int h = tid & 1;

    u64 acc[2][8];

#pragma unroll 1
    for (int pass = 0; pass < 3; ++pass) {
        gemm_px(A, (pass == 1) ? W1 : W0, tx, ty, acc);

        if (pass < 2) {
            __syncthreads();   // all warps done reading current W buffer
            if (pass == 0) {   // V weights -> W0
                for (int i = tid; i < 1024; i += 256) {
                    int j = i >> 4, ck = (i & 15) << 2;
                    cpa16(W032 + (j * 64 + ck) * 4, wqkv + 8192 + j * 64 + ck);
                }
                CPA_COMMIT();
            }
            // stage C[j][px] pad 130 (STS.64)
#pragma unroll
            for (int jj = 0; jj < 8; ++jj)
#pragma unroll
                for (int pq = 0; pq < 2; ++pq)
                    *(u64*)(C + (8 * ty + jj) * 130 + 2 * (tx + 32 * pq)) = acc[pq][jj];
            __syncthreads();

            // stats: thread handles channels h*32..h*32+31 of pixel spx
            {
                const int boff = pass * 64, j0 = h << 5;
                const size_t rownc = base + ((size_t)(n0 + spx) << 6);
                float rv[32];
                float part = 0.f;
#pragma unroll
                for (int t = 0; t < 32; ++t) {
                    rv[t] = C[(j0 + t) * 130 + spx] + sB[boff + j0 + t];
                    part += rv[t];
                }
                float mean = (part + __shfl_xor_sync(0xFFFFFFFFu, part, 1)) * (1.f / 64.f);
                float ss = 0.f;
#pragma unroll
                for (int t = 0; t < 32; ++t) {
                    float u = rv[t] - mean;
                    u = u * u;
                    rv[t] = u;
                    ss += u;
                }
                ss += __shfl_xor_sync(0xFFFFFFFFu, ss, 1);
                float inv = 1.f / (ss + 1e-7f);
                float scale;
                if (pass == 0) {
                    float nr = 0.f;
#pragma unroll
                    for (int t = 0; t < 32; ++t) {
                        float u = rv[t] * inv;
                        nr = fmaf(u, u, nr);
                    }
                    nr += __shfl_xor_sync(0xFFFFFFFFu, nr, 1);
                    scale = inv / fmaxf(sqrtf(nr), 1e-12f);
                } else {
                    scale = inv;
                }
                float* dst = (pass == 0 ? g_q2n : g_k2d) + rownc + j0;
#pragma unroll
                for (int t = 0; t < 8; ++t)
                    reinterpret_cast<float4*>(dst)[t] =
                        make_float4(rv[4 * t] * scale, rv[4 * t + 1] * scale,
                                    rv[4 * t + 2] * scale, rv[4 * t + 3] * scale);
            }
            if (pass == 0) { CPA_WAIT(1); } else { CPA_WAIT(0); }
            __syncthreads();
        } else {
            // V: assemble float4 rows from packed acc -> g_v [n][c]
            float bs[8];
#pragma unroll
            for (int jj = 0; jj < 8; ++jj) bs[jj] = sB[128 + 8 * ty + jj];
#pragma unroll
            for (int pq = 0; pq < 2; ++pq) {
                const int n = n0 + 2 * (tx + 32 * pq);
                float* dst = g_v + base + ((size_t)n << 6) + 8 * ty;
                float2 u0 = unpack2(acc[pq][0]), u1 = unpack2(acc[pq][1]);
                float2 u2 = unpack2(acc[pq][2]), u3 = unpack2(acc[pq][3]);
                float2 u4 = unpack2(acc[pq][4]), u5 = unpack2(acc[pq][5]);
                float2 u6 = unpack2(acc[pq][6]), u7 = unpack2(acc[pq][7]);
                *(float4*)(dst)      = make_float4(u0.x + bs[0], u1.x + bs[1], u2.x + bs[2], u3.x + bs[3]);
                *(float4*)(dst + 4)  = make_float4(u4.x + bs[4], u5.x + bs[5], u6.x + bs[6], u7.x + bs[7]);
                *(float4*)(dst + 64) = make_float4(u0.y + bs[0], u1.y + bs[1], u2.y + bs[2], u3.y + bs[3]);
                *(float4*)(dst + 68) = make_float4(u4.y + bs[4], u5.y + bs[5], u6.y + bs[6], u7.y + bs[7]);
            }
        }
    }
}

// ---------------------------------------------------------------------------
// kvacc: reg-prefetch, FFMA2 (unchanged)
__global__ __launch_bounds__(256) void essa_kvacc() {
    const int b = blockIdx.y;
    const int n0 = blockIdx.x << 9;
    const size_t base = (size_t)b << 22;

    __shared__ float ks[64 * 33];
    __shared__ __align__(16) float vs[32 * 68];

    const int tid = threadIdx.x;
    const int ty = tid >> 4, tx = tid & 15;
    const int c0 = ty << 2, d0 = tx << 2;

    const int nnA = tid >> 4, c4A = (tid & 15) << 2;
    const int i1 = tid + 256;
    const int nnB = i1 >> 4, c4B = (i1 & 15) << 2;

    u64 acc[4][2];
#pragma unroll
    for (int i = 0; i < 4; ++i) { acc[i][0] = 0; acc[i][1] = 0; }
    float cssr = 0.f;

    float4 ka, va, kb, vb;
    {
        size_t gA = base + ((size_t)(n0 + nnA) << 6) + c4A;
        size_t gB = base + ((size_t)(n0 + nnB) << 6) + c4B;
        ka = *reinterpret_cast<const float4*>(g_k2d + gA);
        va = *reinterpret_cast<const float4*>(g_v + gA);
        kb = *reinterpret_cast<const float4*>(g_k2d + gB);
        vb = *reinterpret_cast<const float4*>(g_v + gB);
    }

#pragma unroll 1
    for (int t = 0; t < 16; ++t) {
        __syncthreads();
        ks[(c4A + 0) * 33 + nnA] = ka.x;
        ks[(c4A + 1) * 33 + nnA] = ka.y;
        ks[(c4A + 2) * 33 + nnA] = ka.z;
        ks[(c4A + 3) * 33 + nnA] = ka.w;
        *reinterpret_cast<float4*>(vs + nnA * 68 + c4A) = va;
        ks[(c4B + 0) * 33 + nnB] = kb.x;
        ks[(c4B + 1) * 33 + nnB] = kb.y;
        ks[(c4B + 2) * 33 + nnB] = kb.z;
        ks[(c4B + 3) * 33 + nnB] = kb.w;
        *reinterpret_cast<float4*>(vs + nnB * 68 + c4B) = vb;
        if (t < 15) {
            const int nb = n0 + ((t + 1) << 5);
            size_t gA = base + ((size_t)(nb + nnA) << 6) + c4A;
            size_t gB = base + ((size_t)(nb + nnB) << 6) + c4B;
            ka = *reinterpret_cast<const float4*>(g_k2d + gA);
            va = *reinterpret_cast<const float4*>(g_v + gA);
            kb = *reinterpret_cast<const float4*>(g_k2d + gB);
            vb = *reinterpret_cast<const float4*>(g_v + gB);
        }
        __syncthreads();
        const float* kp = ks + c0 * 33;
#pragma unroll 4
        for (int nn = 0; nn < 32; ++nn) {
            ulonglong2 v01 = *reinterpret_cast<const ulonglong2*>(vs + nn * 68 + d0);
            float k0 = kp[nn], k1 = kp[33 + nn], k2 = kp[66 + nn], k3 = kp[99 + nn];
            u64 kk0 = dup2(k0), kk1 = dup2(k1), kk2 = dup2(k2), kk3 = dup2(k3);
            acc[0][0] = ffma2(kk0, v01.x, acc[0][0]); acc[0][1] = ffma2(kk0, v01.y, acc[0][1]);
            acc[1][0] = ffma2(kk1, v01.x, acc[1][0]); acc[1][1] = ffma2(kk1, v01.y, acc[1][1]);
            acc[2][0] = ffma2(kk2, v01.x, acc[2][0]); acc[2][1] = ffma2(kk2, v01.y, acc[2][1]);
            acc[3][0] = ffma2(kk3, v01.x, acc[3][0]); acc[3][1] = ffma2(kk3, v01.y, acc[3][1]);
        }
        if (tid < 64) {
            const float* cp = ks + tid * 33;
#pragma unroll 8
            for (int nn = 0; nn < 32; ++nn) { float u = cp[nn]; cssr = fmaf(u, u, cssr); }
        }
    }

    float* Mp = g_M + (b << 12);
#pragma unroll
    for (int i = 0; i < 4; ++i) {
        float2 a0 = unpack2(acc[i][0]), a1 = unpack2(acc[i][1]);
        atomicAdd(&Mp[(c0 + i) * 64 + d0 + 0], a0.x);
        atomicAdd(&Mp[(c0 + i) * 64 + d0 + 1], a0.y);
        atomicAdd(&Mp[(c0 + i) * 64 + d0 + 2], a1.x);
        atomicAdd(&Mp[(c0 + i) * 64 + d0 + 3], a1.y);
    }
    if (tid < 64) atomicAdd(&g_css[(b << 6) + tid], cssr);
}

// ---------------------------------------------------------------------------
// wcat: emit k-major concat weight WcT[b][k][j]:
//   k<64:   WcT[k][j] = wln[j][k]
//   k=64+c: WcT[64+c][j] = (sum_d M[c][d]*wln[j][d]) / (nrm_c*256)
__global__ void essa_wcat(const float* __restrict__ wln) {
    __shared__ float sM[4096], sW[4096], sInv[64];
    const int b = blockIdx.x;
    const int tid = threadIdx.x;

    for (int i = tid; i < 4096; i += 256) {
        sM[i] = g_M[(b << 12) + i];
        sW[i] = wln[i];
    }
    if (tid < 64)
        sInv[tid] = 1.f / (fmaxf(sqrtf(g_css[(b << 6) + tid]), 1e-12f) * 256.f);
    __syncthreads();

    float* Wc = g_WcT + (b << 13);
    for (int i = tid; i < 4096; i += 256) {
        int k = i >> 6, j = i & 63;
        Wc[k * 64 + j] = sW[j * 64 + k];
    }
#pragma unroll 1
    for (int t = 0; t < 16; ++t) {
        int i = tid + (t << 8);
        int c = i >> 6, j = i & 63;
        u64 s0 = 0, s1 = 0;
#pragma unroll
        for (int dd = 0; dd < 16; ++dd) {
            s0 = ffma2(lds_u64(sM + c * 64 + 4 * dd),     lds_u64(sW + j * 64 + 4 * dd),     s0);
            s1 = ffma2(lds_u64(sM + c * 64 + 4 * dd + 2), lds_u64(sW + j * 64 + 4 * dd + 2), s1);
        }
        Wc[(64 + c) * 64 + j] = hsum2(s0, s1) * sInv[c];
    }
}

// ---------------------------------------------------------------------------
// out GEMM core (256 thr, j-packing): tx=tid&15, ty=tid>>4 (0..15).
// acc[pp][jq] = (out(px, j0), out(px, j0+1)), px = tx+16*pp, j0 = 4*ty+2*jq.
__device__ __forceinline__ void gemm_j(const float* __restrict__ A,
                                       const float* __restrict__ Wt,
                                       int tx, int ty, int k4lo, int k4hi,
                                       u64 acc[8][2]) {
#pragma unroll 2
    for (int k4 = k4lo; k4 < k4hi; ++k4) {
        ulonglong2 bt[4];
#pragma unroll
        for (int kk = 0; kk < 4; ++kk)
            bt[kk] = lds_u128(Wt + (4 * k4 + kk) * 64 + 4 * ty);
#pragma unroll
        for (int pp = 0; pp < 8; ++pp) {
            ulonglong2 a = lds_u128(A + (tx + 16 * pp) * 132 + 4 * k4);
            float2 al = unpack2(a.x), ah = unpack2(a.y);
            u64 d0 = dup2(al.x), d1 = dup2(al.y), d2 = dup2(ah.x), d3 = dup2(ah.y);
            acc[pp][0] = ffma2(d0, bt[0].x, acc[pp][0]);
            acc[pp][1] = ffma2(d0, bt[0].y, acc[pp][1]);
            acc[pp][0] = ffma2(d1, bt[1].x, acc[pp][0]);
            acc[pp][1] = ffma2(d1, bt[1].y, acc[pp][1]);
            acc[pp][0] = ffma2(d2, bt[2].x, acc[pp][0]);
            acc[pp][1] = ffma2(d2, bt[2].y, acc[pp][1]);
            acc[pp][0] = ffma2(d3, bt[3].x, acc[pp][0]);
            acc[pp][1] = ffma2(d3, bt[3].y, acc[pp][1]);
        }
    }
}

// ---------------------------------------------------------------------------
// out: K=128 GEMM out[n][j] = [v|q2n][n][:] . WcT[:][j] + bln[j]
// smem fl: A[128*132]=16896 | Wt[128*64]=8192 | sBl 64; C[128*66] overlays A
__global__ __launch_bounds__(256) void essa_out(const float* __restrict__ bln,
                                                float* __restrict__ out) {
    extern __shared__ float sm[];
    float* A   = sm;
    float* Wt  = sm + 16896;
    float* sBl = sm + 25088;
    float* C   = sm;   // overlay

    const int tid = threadIdx.x;
    const int tx = tid & 15, ty = tid >> 4;
    const int b = blockIdx.y;
    const int n0 = blockIdx.x << 7;
    const size_t base = (size_t)b << 22;
    const uint32_t A32 = smem_u32(A), Wt32 = smem_u32(Wt), B32 = smem_u32(sBl);
    const float* Ws = g_WcT + (b << 13);

    // G0: v -> A[:,0:64], Wt rows 0..63, bias
    for (int i = tid; i < 2048; i += 256) {
        int px = i >> 4, ck = (i & 15) << 2;
        cpa16(A32 + (px * 132 + ck) * 4, g_v + base + ((size_t)(n0 + px) << 6) + ck);
    }
    for (int i = tid; i < 1024; i += 256) {
        int k = i >> 4, ck = (i & 15) << 2;
        cpa16(Wt32 + (k * 64 + ck) * 4, Ws + k * 64 + ck);
    }
    if (tid < 16) cpa16(B32 + tid * 16, bln + tid * 4);
    CPA_COMMIT();
    // G1: q2n -> A[:,64:128], Wt rows 64..127
    for (int i = tid; i < 2048; i += 256) {
        int px = i >> 4, ck = (i & 15) << 2;
        cpa16(A32 + (px * 132 + 64 + ck) * 4, g_q2n + base + ((size_t)(n0 + px) << 6) + ck);
    }
    for (int i = tid; i < 1024; i += 256) {
        int k = i >> 4, ck = (i & 15) << 2;
        cpa16(Wt32 + ((64 + k) * 64 + ck) * 4, Ws + (64 + k) * 64 + ck);
    }
    CPA_COMMIT();

    u64 acc[8][2];
#pragma unroll
    for (int pp = 0; pp < 8; ++pp) { acc[pp][0] = 0; acc[pp][1] = 0; }

    CPA_WAIT(1);
    __syncthreads();
    gemm_j(A, Wt, tx, ty, 0, 16, acc);
    CPA_WAIT(0);
    __syncthreads();
    gemm_j(A, Wt, tx, ty, 16, 32, acc);
    __syncthreads();   // A reads done -> C overlay

    // stage C[px][j] pad 66 (STS.64 of j-pairs, even offsets)
#pragma unroll
    for (int pp = 0; pp < 8; ++pp)
#pragma unroll
        for (int jq = 0; jq < 2; ++jq)
            *(u64*)(C + (tx + 16 * pp) * 66 + 4 * ty + 2 * jq) = acc[pp][jq];
    __syncthreads();

    for (int i = tid; i < 8192; i += 256) {
        int j = i >> 7, px = i & 127;
        out[base + ((size_t)j << 16) + n0 + px] = C[px * 66 + j] + sBl[j];
    }
}

// ---------------------------------------------------------------------------
extern "C" void kernel_launch(void* const* d_in, const int* in_sizes, int n_in,
                              void* d_out, int out_size) {
    const float* x    = (const float*)d_in[0];
    const float* wqkv = (const float*)d_in[1];
    const float* bqkv = (const float*)d_in[2];
    const float* wln  = (const float*)d_in[3];
    const float* bln  = (const float*)d_in[4];
    float* out = (float*)d_out;

    cudaFuncSetAttribute(essa_qkv, cudaFuncAttributeMaxDynamicSharedMemorySize, 100608);
    cudaFuncSetAttribute(essa_out, cudaFuncAttributeMaxDynamicSharedMemorySize, 100608);

    dim3 gridQ(NPIX / 128, NBAT);
    essa_qkv<<<gridQ, 256, 100608>>>(x, wqkv, bqkv);

    dim3 gridM(NPIX / 512, NBAT);
    essa_kvacc<<<gridM, 256>>>();

    essa_wcat<<<NBAT, 256>>>(wln);

    essa_out<<<gridQ, 256, 100608>>>(bln, out);
}

// round 13
// speedup vs baseline: 1.6448x; 1.0361x over previous
#include <cuda_runtime.h>
#include <cstdint>

// ESSAttn: b=8, C=64, H=W=256, N=65536
// x, out: [b][C][N]  (b<<22 | c<<16 | n)
// scratch q2n,k2d,v: [b][N][C]  (b<<22 | n<<6 | c)

#define NPIX 65536
#define NBAT 8

typedef unsigned long long u64;

// ---------------- scratch ----------------
__device__ float g_q2n[(size_t)NBAT * 64 * NPIX];
__device__ float g_k2d[(size_t)NBAT * 64 * NPIX];
__device__ float g_v  [(size_t)NBAT * 64 * NPIX];
__device__ float g_M  [NBAT * 64 * 64];
__device__ float g_css[NBAT * 64];
__device__ float g_WcT[NBAT * 128 * 64];   // [b][k][j]  k-major concat weight

// ---------------- packed fp32 + async helpers ----------------
__device__ __forceinline__ u64 ffma2(u64 a, u64 b, u64 c) {
    u64 d;
    asm("fma.rn.f32x2 %0, %1, %2, %3;" : "=l"(d) : "l"(a), "l"(b), "l"(c));
    return d;
}
__device__ __forceinline__ u64 fadd2(u64 a, u64 b) {
    u64 d;
    asm("add.rn.f32x2 %0, %1, %2;" : "=l"(d) : "l"(a), "l"(b));
    return d;
}
__device__ __forceinline__ float2 unpack2(u64 v) {
    float lo, hi;
    asm("mov.b64 {%0, %1}, %2;" : "=f"(lo), "=f"(hi) : "l"(v));
    return make_float2(lo, hi);
}
__device__ __forceinline__ u64 dup2(float f) {
    u64 d;
    asm("mov.b64 %0, {%1, %1};" : "=l"(d) : "f"(f));
    return d;
}
__device__ __forceinline__ float hsum2(u64 a, u64 b) {
    float2 r = unpack2(fadd2(a, b));
    return r.x + r.y;
}
__device__ __forceinline__ u64 lds_u64(const float* p) {
    return *reinterpret_cast<const u64*>(p);
}
__device__ __forceinline__ ulonglong2 lds_u128(const float* p) {
    return *reinterpret_cast<const ulonglong2*>(p);
}
__device__ __forceinline__ uint32_t smem_u32(const void* p) {
    uint32_t a;
    asm("{ .reg .u64 t; cvta.to.shared.u64 t, %1; cvt.u32.u64 %0, t; }" : "=r"(a) : "l"(p));
    return a;
}
__device__ __forceinline__ void cpa16(uint32_t dst, const float* src) {
    asm volatile("cp.async.cg.shared.global [%0], [%1], 16;" :: "r"(dst), "l"(src));
}
#define CPA_COMMIT() asm volatile("cp.async.commit_group;" ::: "memory")
#define CPA_WAIT(n)  asm volatile("cp.async.wait_group %0;" :: "n"(n) : "memory")

// ---------------------------------------------------------------------------
// qkv GEMM core (256 thr, px-packing): tx=tid&31, ty=tid>>5 (warp==ty).
// acc[pq][jj] = (out(px0), out(px0+1)), px0 = 2*(tx+32*pq), j = 8*ty+jj.
// A[k][px] pad 132, W[j][k] rows of 64. B loads are whole-warp broadcasts.
__device__ __forceinline__ void gemm_px(const float* __restrict__ A,
                                        const float* __restrict__ W,
                                        int tx, int ty, u64 acc[2][8]) {
#pragma unroll
    for (int pq = 0; pq < 2; ++pq)
#pragma unroll
        for (int jj = 0; jj < 8; ++jj) acc[pq][jj] = 0;
#pragma unroll 2
    for (int k4 = 0; k4 < 16; ++k4) {
        u64 av[4][2];   // [kk][pq]
#pragma unroll
        for (int kk = 0; kk < 4; ++kk)
#pragma unroll
            for (int pq = 0; pq < 2; ++pq)
                av[kk][pq] = lds_u64(A + (4 * k4 + kk) * 132 + 2 * (tx + 32 * pq));
#pragma unroll
        for (int jj = 0; jj < 8; ++jj) {
            ulonglong2 bb = lds_u128(W + (8 * ty + jj) * 64 + 4 * k4);
            float2 bl = unpack2(bb.x), bh = unpack2(bb.y);
            u64 d0 = dup2(bl.x), d1 = dup2(bl.y), d2 = dup2(bh.x), d3 = dup2(bh.y);
#pragma unroll
            for (int pq = 0; pq < 2; ++pq) {
                acc[pq][jj] = ffma2(av[0][pq], d0, acc[pq][jj]);
                acc[pq][jj] = ffma2(av[1][pq], d1, acc[pq][jj]);
                acc[pq][jj] = ffma2(av[2][pq], d2, acc[pq][jj]);
                acc[pq][jj] = ffma2(av[3][pq], d3, acc[pq][jj]);
            }
        }
    }
}

// ---------------------------------------------------------------------------
// qkv: 256 thr/CTA, 128 px, 3 passes of 64 outputs (R12 measured-best).
// smem fl: A[64*132]=8448 | W0 4096 | W1 4096 | C[64*130]=8320 | sB 192 -> 100608 B
__global__ __launch_bounds__(256) void essa_qkv(const float* __restrict__ x,
                                                const float* __restrict__ wqkv,
                                                const float* __restrict__ bqkv) {
    extern __shared__ float sm[];
    float* A  = sm;
    float* W0 = sm + 8448;
    float* W1 = sm + 12544;
    float* C  = sm + 16640;
    float* sB = sm + 24960;

    const int tid = threadIdx.x;
    const int tx = tid & 31, ty = tid >> 5;
    const int b = blockIdx.y;
    const int n0 = blockIdx.x << 7;
    const size_t base = (size_t)b << 22;
    const uint32_t A32 = smem_u32(A), W032 = smem_u32(W0), W132 = smem_u32(W1);

    if (blockIdx.x == 0 && b == 0) {
        for (int i = tid; i < NBAT * 64 * 64; i += 256) g_M[i] = 0.f;
        for (int i = tid; i < NBAT * 64; i += 256) g_css[i] = 0.f;
    }

    // G0: A rows (row copy from x [c][n]; 64 rows x 32 chunks) + W(Q)
    for (int i = tid; i < 2048; i += 256) {
        int k = i >> 5, ck = (i & 31) << 2;
        cpa16(A32 + (k * 132 + ck) * 4, x + base + ((size_t)k << 16) + n0 + ck);
    }
    for (int i = tid; i < 1024; i += 256) {
        int j = i >> 4, ck = (i & 15) << 2;
        cpa16(W032 + (j * 64 + ck) * 4, wqkv + j * 64 + ck);
    }
    CPA_COMMIT();
    // G1: W(K)
    for (int i = tid; i < 1024; i += 256) {
        int j = i >> 4, ck = (i & 15) << 2;
        cpa16(W132 + (j * 64 + ck) * 4, wqkv + 4096 + j * 64 + ck);
    }
    CPA_COMMIT();
    if (tid < 48) *(float4*)(sB + tid * 4) = *(const float4*)(bqkv + tid * 4);
    CPA_WAIT(1);
    __syncthreads();

    // stats mapping: 2 threads per pixel (partner = tid^1, same warp)
    const int spx = tid >> 1;
    const int h = tid & 1;

    u64 acc[2][8];

#pragma unroll 1
    for (int pass = 0; pass < 3; ++pass) {
        gemm_px(A, (pass == 1) ? W1 : W0, tx, ty, acc);

        if (pass < 2) {
            __syncthreads();   // all warps done reading current W buffer
            if (pass == 0) {   // V weights -> W0
                for (int i = tid; i < 1024; i += 256) {
                    int j = i >> 4, ck = (i & 15) << 2;
                    cpa16(W032 + (j * 64 + ck) * 4, wqkv + 8192 + j * 64 + ck);
                }
                CPA_COMMIT();
            }
            // stage C[j][px] pad 130 (STS.64)
#pragma unroll
            for (int jj = 0; jj < 8; ++jj)
#pragma unroll
                for (int pq = 0; pq < 2; ++pq)
                    *(u64*)(C + (8 * ty + jj) * 130 + 2 * (tx + 32 * pq)) = acc[pq][jj];
            __syncthreads();

            // stats: thread handles channels h*32..h*32+31 of pixel spx
            {
                const int boff = pass * 64, j0 = h << 5;
                const size_t rownc = base + ((size_t)(n0 + spx) << 6);
                float rv[32];
                float part = 0.f;
#pragma unroll
                for (int t = 0; t < 32; ++t) {
                    rv[t] = C[(j0 + t) * 130 + spx] + sB[boff + j0 + t];
                    part += rv[t];
                }
                float mean = (part + __shfl_xor_sync(0xFFFFFFFFu, part, 1)) * (1.f / 64.f);
                float ss = 0.f;
#pragma unroll
                for (int t = 0; t < 32; ++t) {
                    float u = rv[t] - mean;
                    u = u * u;
                    rv[t] = u;
                    ss += u;
                }
                ss += __shfl_xor_sync(0xFFFFFFFFu, ss, 1);
                float inv = 1.f / (ss + 1e-7f);
                float scale;
                if (pass == 0) {
                    float nr = 0.f;
#pragma unroll
                    for (int t = 0; t < 32; ++t) {
                        float u = rv[t] * inv;
                        nr = fmaf(u, u, nr);
                    }
                    nr += __shfl_xor_sync(0xFFFFFFFFu, nr, 1);
                    scale = inv / fmaxf(sqrtf(nr), 1e-12f);
                } else {
                    scale = inv;
                }
                float* dst = (pass == 0 ? g_q2n : g_k2d) + rownc + j0;
#pragma unroll
                for (int t = 0; t < 8; ++t)
                    reinterpret_cast<float4*>(dst)[t] =
                        make_float4(rv[4 * t] * scale, rv[4 * t + 1] * scale,
                                    rv[4 * t + 2] * scale, rv[4 * t + 3] * scale);
            }
            if (pass == 0) { CPA_WAIT(1); } else { CPA_WAIT(0); }
            __syncthreads();
        } else {
            // V: assemble float4 rows from packed acc -> g_v [n][c]
            float bs[8];
#pragma unroll
            for (int jj = 0; jj < 8; ++jj) bs[jj] = sB[128 + 8 * ty + jj];
#pragma unroll
            for (int pq = 0; pq < 2; ++pq) {
                const int n = n0 + 2 * (tx + 32 * pq);
                float* dst = g_v + base + ((size_t)n << 6) + 8 * ty;
                float2 u0 = unpack2(acc[pq][0]), u1 = unpack2(acc[pq][1]);
                float2 u2 = unpack2(acc[pq][2]), u3 = unpack2(acc[pq][3]);
                float2 u4 = unpack2(acc[pq][4]), u5 = unpack2(acc[pq][5]);
                float2 u6 = unpack2(acc[pq][6]), u7 = unpack2(acc[pq][7]);
                *(float4*)(dst)      = make_float4(u0.x + bs[0], u1.x + bs[1], u2.x + bs[2], u3.x + bs[3]);
                *(float4*)(dst + 4)  = make_float4(u4.x + bs[4], u5.x + bs[5], u6.x + bs[6], u7.x + bs[7]);
                *(float4*)(dst + 64) = make_float4(u0.y + bs[0], u1.y + bs[1], u2.y + bs[2], u3.y + bs[3]);
                *(float4*)(dst + 68) = make_float4(u4.y + bs[4], u5.y + bs[5], u6.y + bs[6], u7.y + bs[7]);
            }
        }
    }
}

// ---------------------------------------------------------------------------
// kvacc: reg-prefetch, FFMA2 (unchanged)
__global__ __launch_bounds__(256) void essa_kvacc() {
    const int b = blockIdx.y;
    const int n0 = blockIdx.x << 9;
    const size_t base = (size_t)b << 22;

    __shared__ float ks[64 * 33];
    __shared__ __align__(16) float vs[32 * 68];

    const int tid = threadIdx.x;
    const int ty = tid >> 4, tx = tid & 15;
    const int c0 = ty << 2, d0 = tx << 2;

    const int nnA = tid >> 4, c4A = (tid & 15) << 2;
    const int i1 = tid + 256;
    const int nnB = i1 >> 4, c4B = (i1 & 15) << 2;

    u64 acc[4][2];
#pragma unroll
    for (int i = 0; i < 4; ++i) { acc[i][0] = 0; acc[i][1] = 0; }
    float cssr = 0.f;

    float4 ka, va, kb, vb;
    {
        size_t gA = base + ((size_t)(n0 + nnA) << 6) + c4A;
        size_t gB = base + ((size_t)(n0 + nnB) << 6) + c4B;
        ka = *reinterpret_cast<const float4*>(g_k2d + gA);
        va = *reinterpret_cast<const float4*>(g_v + gA);
        kb = *reinterpret_cast<const float4*>(g_k2d + gB);
        vb = *reinterpret_cast<const float4*>(g_v + gB);
    }

#pragma unroll 1
    for (int t = 0; t < 16; ++t) {
        __syncthreads();
        ks[(c4A + 0) * 33 + nnA] = ka.x;
        ks[(c4A + 1) * 33 + nnA] = ka.y;
        ks[(c4A + 2) * 33 + nnA] = ka.z;
        ks[(c4A + 3) * 33 + nnA] = ka.w;
        *reinterpret_cast<float4*>(vs + nnA * 68 + c4A) = va;
        ks[(c4B + 0) * 33 + nnB] = kb.x;
        ks[(c4B + 1) * 33 + nnB] = kb.y;
        ks[(c4B + 2) * 33 + nnB] = kb.z;
        ks[(c4B + 3) * 33 + nnB] = kb.w;
        *reinterpret_cast<float4*>(vs + nnB * 68 + c4B) = vb;
        if (t < 15) {
            const int nb = n0 + ((t + 1) << 5);
            size_t gA = base + ((size_t)(nb + nnA) << 6) + c4A;
            size_t gB = base + ((size_t)(nb + nnB) << 6) + c4B;
            ka = *reinterpret_cast<const float4*>(g_k2d + gA);
            va = *reinterpret_cast<const float4*>(g_v + gA);
            kb = *reinterpret_cast<const float4*>(g_k2d + gB);
            vb = *reinterpret_cast<const float4*>(g_v + gB);
        }
        __syncthreads();
        const float* kp = ks + c0 * 33;
#pragma unroll 4
        for (int nn = 0; nn < 32; ++nn) {
            ulonglong2 v01 = *reinterpret_cast<const ulonglong2*>(vs + nn * 68 + d0);
            float k0 = kp[nn], k1 = kp[33 + nn], k2 = kp[66 + nn], k3 = kp[99 + nn];
            u64 kk0 = dup2(k0), kk1 = dup2(k1), kk2 = dup2(k2), kk3 = dup2(k3);
            acc[0][0] = ffma2(kk0, v01.x, acc[0][0]); acc[0][1] = ffma2(kk0, v01.y, acc[0][1]);
            acc[1][0] = ffma2(kk1, v01.x, acc[1][0]); acc[1][1] = ffma2(kk1, v01.y, acc[1][1]);
            acc[2][0] = ffma2(kk2, v01.x, acc[2][0]); acc[2][1] = ffma2(kk2, v01.y, acc[2][1]);
            acc[3][0] = ffma2(kk3, v01.x, acc[3][0]); acc[3][1] = ffma2(kk3, v01.y, acc[3][1]);
        }
        if (tid < 64) {
            const float* cp = ks + tid * 33;
#pragma unroll 8
            for (int nn = 0; nn < 32; ++nn) { float u = cp[nn]; cssr = fmaf(u, u, cssr); }
        }
    }

    float* Mp = g_M + (b << 12);
#pragma unroll
    for (int i = 0; i < 4; ++i) {
        float2 a0 = unpack2(acc[i][0]), a1 = unpack2(acc[i][1]);
        atomicAdd(&Mp[(c0 + i) * 64 + d0 + 0], a0.x);
        atomicAdd(&Mp[(c0 + i) * 64 + d0 + 1], a0.y);
        atomicAdd(&Mp[(c0 + i) * 64 + d0 + 2], a1.x);
        atomicAdd(&Mp[(c0 + i) * 64 + d0 + 3], a1.y);
    }
    if (tid < 64) atomicAdd(&g_css[(b << 6) + tid], cssr);
}

// ---------------------------------------------------------------------------
// wcat: emit k-major concat weight WcT[b][k][j]:
//   k<64:   WcT[k][j] = wln[j][k]
//   k=64+c: WcT[64+c][j] = (sum_d M[c][d]*wln[j][d]) / (nrm_c*256)
__global__ void essa_wcat(const float* __restrict__ wln) {
    __shared__ float sM[4096], sW[4096], sInv[64];
    const int b = blockIdx.x;
    const int tid = threadIdx.x;

    for (int i = tid; i < 4096; i += 256) {
        sM[i] = g_M[(b << 12) + i];
        sW[i] = wln[i];
    }
    if (tid < 64)
        sInv[tid] = 1.f / (fmaxf(sqrtf(g_css[(b << 6) + tid]), 1e-12f) * 256.f);
    __syncthreads();

    float* Wc = g_WcT + (b << 13);
    for (int i = tid; i < 4096; i += 256) {
        int k = i >> 6, j = i & 63;
        Wc[k * 64 + j] = sW[j * 64 + k];
    }
#pragma unroll 1
    for (int t = 0; t < 16; ++t) {
        int i = tid + (t << 8);
        int c = i >> 6, j = i & 63;
        u64 s0 = 0, s1 = 0;
#pragma unroll
        for (int dd = 0; dd < 16; ++dd) {
            s0 = ffma2(lds_u64(sM + c * 64 + 4 * dd),     lds_u64(sW + j * 64 + 4 * dd),     s0);
            s1 = ffma2(lds_u64(sM + c * 64 + 4 * dd + 2), lds_u64(sW + j * 64 + 4 * dd + 2), s1);
        }
        Wc[(64 + c) * 64 + j] = hsum2(s0, s1) * sInv[c];
    }
}

// ---------------------------------------------------------------------------
// out GEMM core (128 thr, j-packing, R11 measured-best):
// tx=tid&15, ty=tid>>3? no: ty=tid>>4 (0..7). acc[pp][jq] = (out(px,j0),out(px,j0+1)),
// px = tx+16*pp, j0 = 8*ty+2*jq.  A[px][k] pad 132, Wt[k][j] rows of 64.
__device__ __forceinline__ void gemm_j(const float* __restrict__ A,
                                       const float* __restrict__ Wt,
                                       int tx, int ty, int k4lo, int k4hi,
                                       u64 acc[8][4]) {
#pragma unroll 2
    for (int k4 = k4lo; k4 < k4hi; ++k4) {
        ulonglong2 bt0[4], bt1[4];
#pragma unroll
        for (int kk = 0; kk < 4; ++kk) {
            bt0[kk] = lds_u128(Wt + (4 * k4 + kk) * 64 + 8 * ty);
            bt1[kk] = lds_u128(Wt + (4 * k4 + kk) * 64 + 8 * ty + 4);
        }
#pragma unroll
        for (int pp = 0; pp < 8; ++pp) {
            ulonglong2 a = lds_u128(A + (tx + 16 * pp) * 132 + 4 * k4);
            float2 al = unpack2(a.x), ah = unpack2(a.y);
            u64 d0 = dup2(al.x), d1 = dup2(al.y), d2 = dup2(ah.x), d3 = dup2(ah.y);
            acc[pp][0] = ffma2(d0, bt0[0].x, acc[pp][0]);
            acc[pp][1] = ffma2(d0, bt0[0].y, acc[pp][1]);
            acc[pp][2] = ffma2(d0, bt1[0].x, acc[pp][2]);
            acc[pp][3] = ffma2(d0, bt1[0].y, acc[pp][3]);
            acc[pp][0] = ffma2(d1, bt0[1].x, acc[pp][0]);
            acc[pp][1] = ffma2(d1, bt0[1].y, acc[pp][1]);
            acc[pp][2] = ffma2(d1, bt1[1].x, acc[pp][2]);
            acc[pp][3] = ffma2(d1, bt1[1].y, acc[pp][3]);
            acc[pp][0] = ffma2(d2, bt0[2].x, acc[pp][0]);
            acc[pp][1] = ffma2(d2, bt0[2].y, acc[pp][1]);
            acc[pp][2] = ffma2(d2, bt1[2].x, acc[pp][2]);
            acc[pp][3] = ffma2(d2, bt1[2].y, acc[pp][3]);
            acc[pp][0] = ffma2(d3, bt0[3].x, acc[pp][0]);
            acc[pp][1] = ffma2(d3, bt0[3].y, acc[pp][1]);
            acc[pp][2] = ffma2(d3, bt1[3].x, acc[pp][2]);
            acc[pp][3] = ffma2(d3, bt1[3].y, acc[pp][3]);
        }
    }
}

// ---------------------------------------------------------------------------
// out: K=128 GEMM out[n][j] = [v|q2n][n][:] . WcT[:][j] + bln[j]   (R11 version)
// smem fl: A[128*132]=16896 | Wt[128*64]=8192 | sBl 64; C[128*66] overlays A
__global__ __launch_bounds__(128) void essa_out(const float* __restrict__ bln,
                                                float* __restrict__ out) {
    extern __shared__ float sm[];
    float* A   = sm;
    float* Wt  = sm + 16896;
    float* sBl = sm + 25088;
    float* C   = sm;   // overlay

    const int tid = threadIdx.x;
    const int tx = tid & 15, ty = tid >> 4;
    const int b = blockIdx.y;
    const int n0 = blockIdx.x << 7;
    const size_t base = (size_t)b << 22;
    const uint32_t A32 = smem_u32(A), Wt32 = smem_u32(Wt), B32 = smem_u32(sBl);
    const float* Ws = g_WcT + (b << 13);

    // G0: v -> A[:,0:64], Wt rows 0..63, bias
    for (int i = tid; i < 2048; i += 128) {
        int px = i >> 4, ck = (i & 15) << 2;
        cpa16(A32 + (px * 132 + ck) * 4, g_v + base + ((size_t)(n0 + px) << 6) + ck);
    }
    for (int i = tid; i < 1024; i += 128) {
        int k = i >> 4, ck = (i & 15) << 2;
        cpa16(Wt32 + (k * 64 + ck) * 4, Ws + k * 64 + ck);
    }
    if (tid < 16) cpa16(B32 + tid * 16, bln + tid * 4);
    CPA_COMMIT();
    // G1: q2n -> A[:,64:128], Wt rows 64..127
    for (int i = tid; i < 2048; i += 128) {
        int px = i >> 4, ck = (i & 15) << 2;
        cpa16(A32 + (px * 132 + 64 + ck) * 4, g_q2n + base + ((size_t)(n0 + px) << 6) + ck);
    }
    for (int i = tid; i < 1024; i += 128) {
        int k = i >> 4, ck = (i & 15) << 2;
        cpa16(Wt32 + ((64 + k) * 64 + ck) * 4, Ws + (64 + k) * 64 + ck);
    }
    CPA_COMMIT();

    u64 acc[8][4];
#pragma unroll
    for (int pp = 0; pp < 8; ++pp)
#pragma unroll
        for (int jq = 0; jq < 4; ++jq) acc[pp][jq] = 0;

    CPA_WAIT(1);
    __syncthreads();
    gemm_j(A, Wt, tx, ty, 0, 16, acc);
    CPA_WAIT(0);
    __syncthreads();
    gemm_j(A, Wt, tx, ty, 16, 32, acc);
    __syncthreads();   // A reads done -> C overlay

    // stage C[px][j] pad 66 (STS.64 of j-pairs)
#pragma unroll
    for (int pp = 0; pp < 8; ++pp)
#pragma unroll
        for (int jq = 0; jq < 4; ++jq)
            *(u64*)(C + (tx + 16 * pp) * 66 + 8 * ty + 2 * jq) = acc[pp][jq];
    __syncthreads();

    for (int i = tid; i < 8192; i += 128) {
        int j = i >> 7, px = i & 127;
        out[base + ((size_t)j << 16) + n0 + px] = C[px * 66 + j] + sBl[j];
    }
}

// ---------------------------------------------------------------------------
extern "C" void kernel_launch(void* const* d_in, const int* in_sizes, int n_in,
                              void* d_out, int out_size) {
    const float* x    = (const float*)d_in[0];
    const float* wqkv = (const float*)d_in[1];
    const float* bqkv = (const float*)d_in[2];
    const float* wln  = (const float*)d_in[3];
    const float* bln  = (const float*)d_in[4];
    float* out = (float*)d_out;

    cudaFuncSetAttribute(essa_qkv, cudaFuncAttributeMaxDynamicSharedMemorySize, 100608);
    cudaFuncSetAttribute(essa_out, cudaFuncAttributeMaxDynamicSharedMemorySize, 100608);

    dim3 gridQ(NPIX / 128, NBAT);
    essa_qkv<<<gridQ, 256, 100608>>>(x, wqkv, bqkv);

    dim3 gridM(NPIX / 512, NBAT);
    essa_kvacc<<<gridM, 256>>>();

    essa_wcat<<<NBAT, 256>>>(wln);

    essa_out<<<gridQ, 128, 100608>>>(bln, out);
}